// round 4
// baseline (speedup 1.0000x reference)
#include <cuda_runtime.h>
#include <math.h>

#define S_LEN 2048
#define DMODEL 1024
#define NHEADS 16
#define DHEAD 64
#define WIN 256
#define BATCH 2
#define BH (BATCH * NHEADS)
#define MROWS (BATCH * S_LEN)
#define ATT_SCALE 0.125f   // 64^-0.5

// Scratch (allocation-free rule: __device__ globals)
__device__ float g_q[BH * S_LEN * DHEAD];     // [b,h,s,d]
__device__ float g_k[BH * S_LEN * DHEAD];
__device__ float g_v[BH * S_LEN * DHEAD];
__device__ float g_ctx[MROWS * DMODEL];       // [b,s,h*64+d]

// ---------------------------------------------------------------------------
// SGEMM: C[M,N] = A[M,1024] @ W[1024,N] + bias
// MODE 0: A = x, scatter outputs into g_q/g_k/g_v as [b,h,s,d]
// MODE 1: A = g_ctx, plain output to `out`
// Tiles: 128x128x8, 256 threads, 8x8 micro-tile per thread.
// ---------------------------------------------------------------------------
template <int N_COLS, int MODE>
__global__ __launch_bounds__(256, 2) void sgemm_kernel(
    const float* __restrict__ A_in, const float* __restrict__ W,
    const float* __restrict__ bias, float* __restrict__ out)
{
    __shared__ float As[8][128];   // [k][m]
    __shared__ float Bs[8][128];   // [k][n]

    const float* __restrict__ A = (MODE == 1) ? (const float*)g_ctx : A_in;

    const int tid  = threadIdx.x;
    const int m0   = blockIdx.y * 128;
    const int n0   = blockIdx.x * 128;
    const int arow = tid >> 1;          // 0..127
    const int acol = (tid & 1) << 2;    // 0 or 4
    const int brow = tid >> 5;          // 0..7
    const int bcol = (tid & 31) << 2;   // 0..124
    const int ty   = tid >> 4;          // 0..15
    const int tx   = tid & 15;          // 0..15

    float acc[8][8];
#pragma unroll
    for (int i = 0; i < 8; i++)
#pragma unroll
        for (int j = 0; j < 8; j++) acc[i][j] = 0.f;

    const float* Ap = A + (size_t)(m0 + arow) * DMODEL + acol;
    const float* Wp = W + (size_t)brow * N_COLS + n0 + bcol;

    for (int k0 = 0; k0 < DMODEL; k0 += 8) {
        float4 av = *(const float4*)(Ap + k0);
        float4 bv = *(const float4*)(Wp + (size_t)k0 * N_COLS);
        As[acol + 0][arow] = av.x;
        As[acol + 1][arow] = av.y;
        As[acol + 2][arow] = av.z;
        As[acol + 3][arow] = av.w;
        *(float4*)&Bs[brow][bcol] = bv;
        __syncthreads();

#pragma unroll
        for (int kk = 0; kk < 8; kk++) {
            float a[8], b[8];
            *(float4*)&a[0] = *(const float4*)&As[kk][ty * 8];
            *(float4*)&a[4] = *(const float4*)&As[kk][ty * 8 + 4];
            *(float4*)&b[0] = *(const float4*)&Bs[kk][tx * 8];
            *(float4*)&b[4] = *(const float4*)&Bs[kk][tx * 8 + 4];
#pragma unroll
            for (int i = 0; i < 8; i++)
#pragma unroll
                for (int j = 0; j < 8; j++)
                    acc[i][j] += a[i] * b[j];
        }
        __syncthreads();
    }

    const int nbase = n0 + tx * 8;
    float bvals[8];
#pragma unroll
    for (int j = 0; j < 8; j++) bvals[j] = bias[nbase + j];

    if (MODE == 0) {
        // n -> (part, head, d). 8-wide chunk never crosses a 64 boundary.
        const int part = nbase >> 10;
        const int h    = (nbase & 1023) >> 6;
        const int d0   = nbase & 63;
        float* dst = (part == 0) ? g_q : (part == 1) ? g_k : g_v;
#pragma unroll
        for (int i = 0; i < 8; i++) {
            int m = m0 + ty * 8 + i;
            int b = m >> 11;          // S = 2048
            int s = m & 2047;
            float* p = dst + ((size_t)(b * NHEADS + h) * S_LEN + s) * DHEAD + d0;
            float4 v0 = make_float4(acc[i][0] + bvals[0], acc[i][1] + bvals[1],
                                    acc[i][2] + bvals[2], acc[i][3] + bvals[3]);
            float4 v1 = make_float4(acc[i][4] + bvals[4], acc[i][5] + bvals[5],
                                    acc[i][6] + bvals[6], acc[i][7] + bvals[7]);
            *(float4*)p       = v0;
            *(float4*)(p + 4) = v1;
        }
    } else {
#pragma unroll
        for (int i = 0; i < 8; i++) {
            int m = m0 + ty * 8 + i;
            float* p = out + (size_t)m * N_COLS + nbase;
            float4 v0 = make_float4(acc[i][0] + bvals[0], acc[i][1] + bvals[1],
                                    acc[i][2] + bvals[2], acc[i][3] + bvals[3]);
            float4 v1 = make_float4(acc[i][4] + bvals[4], acc[i][5] + bvals[5],
                                    acc[i][6] + bvals[6], acc[i][7] + bvals[7]);
            *(float4*)p       = v0;
            *(float4*)(p + 4) = v1;
        }
    }
}

// ---------------------------------------------------------------------------
// Windowed attention, flash-style online softmax.
// Block = (b,h) x 64-query tile, 256 threads (16x16).
// Key tiles of 32; query i attends keys j in [i, i+255] (anti-causal window).
// Score micro-tile 4q x 2k per thread; PV micro-tile 4q x 4d per thread.
// ---------------------------------------------------------------------------
__global__ __launch_bounds__(256, 4) void attn_kernel()
{
    __shared__ float Qt[64][64];   // [d][q] (transposed)
    __shared__ float Kt[64][32];   // [d][k] (transposed)
    __shared__ float Vs[32][64];   // [k][d]
    __shared__ float Ps[32][68];   // [k][q], padded stride 68 (16B-aligned rows)

    const int tid = threadIdx.x;
    const int ty  = tid >> 4;      // 0..15 -> 4 query rows each
    const int tx  = tid & 15;      // 0..15 -> 2 key cols (scores) / 4 dv cols (PV)
    const int q0  = blockIdx.x * 64;
    const int bh  = blockIdx.y;
    const int h   = bh & 15;
    const int b   = bh >> 4;

    const float* __restrict__ Q = g_q + (size_t)bh * S_LEN * DHEAD;
    const float* __restrict__ K = g_k + (size_t)bh * S_LEN * DHEAD;
    const float* __restrict__ V = g_v + (size_t)bh * S_LEN * DHEAD;

    // Load Q tile (transposed into smem); 4 float4 per thread
    {
        int q  = tid >> 2;              // 0..63
        int d0 = (tid & 3) << 4;        // 0,16,32,48
        const float* src = Q + (size_t)(q0 + q) * DHEAD + d0;
#pragma unroll
        for (int i = 0; i < 4; i++) {
            float4 v = *(const float4*)(src + 4 * i);
            Qt[d0 + 4 * i + 0][q] = v.x;
            Qt[d0 + 4 * i + 1][q] = v.y;
            Qt[d0 + 4 * i + 2][q] = v.z;
            Qt[d0 + 4 * i + 3][q] = v.w;
        }
    }

    float O[4][4];
    float mrow[4], lrow[4];
#pragma unroll
    for (int i = 0; i < 4; i++) {
        mrow[i] = -1e30f;
        lrow[i] = 0.f;
#pragma unroll
        for (int j = 0; j < 4; j++) O[i][j] = 0.f;
    }
    const int qrow0 = q0 + ty * 4;

    for (int t = 0; t < 10; t++) {       // covers keys [q0, q0+319]
        const int kt0 = q0 + t * 32;
        if (kt0 >= S_LEN) break;

        __syncthreads();   // previous tile's readers done with Kt/Vs/Ps

        // Load K (transposed) and V tiles: 32 keys x 64 dims, 8 floats/thread each
        {
            int kk = tid >> 3;              // 0..31
            int d0 = (tid & 7) << 3;        // 0..56
            int krow = kt0 + kk;
            if (krow > S_LEN - 1) krow = S_LEN - 1;   // clamp; masked below
            const float* ks = K + (size_t)krow * DHEAD + d0;
            float4 k0v = *(const float4*)ks;
            float4 k1v = *(const float4*)(ks + 4);
            Kt[d0 + 0][kk] = k0v.x; Kt[d0 + 1][kk] = k0v.y;
            Kt[d0 + 2][kk] = k0v.z; Kt[d0 + 3][kk] = k0v.w;
            Kt[d0 + 4][kk] = k1v.x; Kt[d0 + 5][kk] = k1v.y;
            Kt[d0 + 6][kk] = k1v.z; Kt[d0 + 7][kk] = k1v.w;
            const float* vsrc = V + (size_t)krow * DHEAD + d0;
            *(float4*)&Vs[kk][d0]     = *(const float4*)vsrc;
            *(float4*)&Vs[kk][d0 + 4] = *(const float4*)(vsrc + 4);
        }
        __syncthreads();

        // Scores: 4q x 2k per thread, contraction over 64 dims
        float sc[4][2];
        sc[0][0] = sc[0][1] = sc[1][0] = sc[1][1] = 0.f;
        sc[2][0] = sc[2][1] = sc[3][0] = sc[3][1] = 0.f;
#pragma unroll 16
        for (int d = 0; d < 64; d++) {
            float4 a  = *(const float4*)&Qt[d][ty * 4];
            float2 kk = *(const float2*)&Kt[d][tx * 2];
            sc[0][0] += a.x * kk.x;  sc[0][1] += a.x * kk.y;
            sc[1][0] += a.y * kk.x;  sc[1][1] += a.y * kk.y;
            sc[2][0] += a.z * kk.x;  sc[2][1] += a.z * kk.y;
            sc[3][0] += a.w * kk.x;  sc[3][1] += a.w * kk.y;
        }

        // Mask + scale
#pragma unroll
        for (int i = 0; i < 4; i++) {
            int qrow = qrow0 + i;
#pragma unroll
            for (int j = 0; j < 2; j++) {
                int krow = kt0 + tx * 2 + j;
                bool keep = (krow >= qrow) && (krow <= qrow + (WIN - 1)) && (krow < S_LEN);
                sc[i][j] = keep ? sc[i][j] * ATT_SCALE : -INFINITY;
            }
        }

        // Online softmax update (row reduce across the 16 tx lanes in a half-warp)
#pragma unroll
        for (int i = 0; i < 4; i++) {
            float tmax = fmaxf(sc[i][0], sc[i][1]);
#pragma unroll
            for (int o = 1; o < 16; o <<= 1)
                tmax = fmaxf(tmax, __shfl_xor_sync(0xffffffffu, tmax, o));
            float nm    = fmaxf(mrow[i], tmax);
            float fac   = __expf(mrow[i] - nm);
            mrow[i]     = nm;
            float p0 = __expf(sc[i][0] - nm);
            float p1 = __expf(sc[i][1] - nm);
            sc[i][0] = p0; sc[i][1] = p1;
            float tsum = p0 + p1;
#pragma unroll
            for (int o = 1; o < 16; o <<= 1)
                tsum += __shfl_xor_sync(0xffffffffu, tsum, o);
            lrow[i] = lrow[i] * fac + tsum;
            O[i][0] *= fac; O[i][1] *= fac; O[i][2] *= fac; O[i][3] *= fac;
        }

        // Stage P into smem as [k][q]
#pragma unroll
        for (int i = 0; i < 4; i++) {
            Ps[tx * 2 + 0][ty * 4 + i] = sc[i][0];
            Ps[tx * 2 + 1][ty * 4 + i] = sc[i][1];
        }
        __syncthreads();

        // O += P @ V : 4q x 4d per thread, contraction over 32 keys
#pragma unroll 8
        for (int k = 0; k < 32; k++) {
            float4 pv = *(const float4*)&Ps[k][ty * 4];
            float4 vv = *(const float4*)&Vs[k][tx * 4];
            O[0][0] += pv.x * vv.x; O[0][1] += pv.x * vv.y; O[0][2] += pv.x * vv.z; O[0][3] += pv.x * vv.w;
            O[1][0] += pv.y * vv.x; O[1][1] += pv.y * vv.y; O[1][2] += pv.y * vv.z; O[1][3] += pv.y * vv.w;
            O[2][0] += pv.z * vv.x; O[2][1] += pv.z * vv.y; O[2][2] += pv.z * vv.z; O[2][3] += pv.z * vv.w;
            O[3][0] += pv.w * vv.x; O[3][1] += pv.w * vv.y; O[3][2] += pv.w * vv.z; O[3][3] += pv.w * vv.w;
        }
    }

    // Finalize: divide by l, write ctx[b, s, h*64 + dv]
#pragma unroll
    for (int i = 0; i < 4; i++) {
        float inv = 1.0f / lrow[i];
        int srow  = qrow0 + i;
        float* dst = g_ctx + ((size_t)(b * S_LEN + srow)) * DMODEL + h * 64 + tx * 4;
        *(float4*)dst = make_float4(O[i][0] * inv, O[i][1] * inv,
                                    O[i][2] * inv, O[i][3] * inv);
    }
}

// ---------------------------------------------------------------------------
extern "C" void kernel_launch(void* const* d_in, const int* in_sizes, int n_in,
                              void* d_out, int out_size)
{
    const float* x    = (const float*)d_in[0];   // [2,2048,1024]
    const float* Wqkv = (const float*)d_in[1];   // [1024,3072]
    const float* bqkv = (const float*)d_in[2];   // [3072]
    const float* Wout = (const float*)d_in[3];   // [1024,1024]
    const float* bout = (const float*)d_in[4];   // [1024]
    float* out = (float*)d_out;                  // [2,2048,1024]
    (void)in_sizes; (void)n_in; (void)out_size;

    dim3 blk(256);
    // QKV projection: M=4096, N=3072, K=1024 -> scatter to g_q/g_k/g_v
    sgemm_kernel<3072, 0><<<dim3(3072 / 128, MROWS / 128), blk>>>(x, Wqkv, bqkv, nullptr);
    // Windowed attention -> g_ctx
    attn_kernel<<<dim3(S_LEN / 64, BH), blk>>>();
    // Output projection: M=4096, N=1024, K=1024
    sgemm_kernel<1024, 1><<<dim3(1024 / 128, MROWS / 128), blk>>>(nullptr, Wout, bout, out);
}

// round 5
// speedup vs baseline: 1.1041x; 1.1041x over previous
#include <cuda_runtime.h>
#include <math.h>

#define S_LEN 2048
#define DMODEL 1024
#define NHEADS 16
#define DHEAD 64
#define WIN 256
#define BATCH 2
#define BH (BATCH * NHEADS)
#define MROWS (BATCH * S_LEN)
#define ATT_SCALE 0.125f   // 64^-0.5

typedef unsigned long long ull;

// ---- packed f32x2 helpers (Blackwell FFMA2 path: PTX-only, ptxas won't emit) ----
__device__ __forceinline__ ull pk2(float x) {
    ull r; asm("mov.b64 %0, {%1, %1};" : "=l"(r) : "f"(x)); return r;
}
__device__ __forceinline__ ull pk2(float x, float y) {
    ull r; asm("mov.b64 %0, {%1, %2};" : "=l"(r) : "f"(x), "f"(y)); return r;
}
__device__ __forceinline__ void upk2(ull v, float& x, float& y) {
    asm("mov.b64 {%0, %1}, %2;" : "=f"(x), "=f"(y) : "l"(v));
}
__device__ __forceinline__ void fma2(ull& d, ull a, ull b) {
    asm("fma.rn.f32x2 %0, %1, %2, %0;" : "+l"(d) : "l"(a), "l"(b));
}
__device__ __forceinline__ ull add2(ull a, ull b) {
    ull r; asm("add.rn.f32x2 %0, %1, %2;" : "=l"(r) : "l"(a), "l"(b)); return r;
}
__device__ __forceinline__ ull mul2(ull a, ull b) {
    ull r; asm("mul.rn.f32x2 %0, %1, %2;" : "=l"(r) : "l"(a), "l"(b)); return r;
}

// Scratch (allocation-free rule: __device__ globals)
__device__ float g_q[BH * S_LEN * DHEAD];     // [b,h,s,d]
__device__ float g_k[BH * S_LEN * DHEAD];
__device__ float g_v[BH * S_LEN * DHEAD];
__device__ float g_ctx[MROWS * DMODEL];       // [b,s,h*64+d]

// ---------------------------------------------------------------------------
// SGEMM: C[M,N] = A[M,1024] @ W[1024,N] + bias
// 128x128x16 tiles, double-buffered smem, 256 threads, 8x8 micro-tile held as
// 8x4 packed f32x2 accumulators (fma.rn.f32x2 = 2 MACs / fma-pipe slot).
// MODE 0: A = x, scatter outputs into g_q/g_k/g_v as [b,h,s,d]
// MODE 1: A = g_ctx, plain output to `out`
// ---------------------------------------------------------------------------
template <int N_COLS, int MODE>
__global__ __launch_bounds__(256, 2) void sgemm_kernel(
    const float* __restrict__ A_in, const float* __restrict__ W,
    const float* __restrict__ bias, float* __restrict__ out)
{
    __shared__ float As[2][16][128];   // [buf][k][m]
    __shared__ float Bs[2][16][128];   // [buf][k][n]

    const float* __restrict__ A = (MODE == 1) ? (const float*)g_ctx : A_in;

    const int tid  = threadIdx.x;
    const int m0   = blockIdx.y * 128;
    const int n0   = blockIdx.x * 128;
    const int arow = tid >> 1;          // 0..127
    const int acol = (tid & 1) << 3;    // 0 or 8
    const int brow = tid >> 5;          // 0..7 (and +8)
    const int bcol = (tid & 31) << 2;   // 0..124
    const int ty   = tid >> 4;          // 0..15
    const int tx   = tid & 15;          // 0..15

    ull acc[8][4];
#pragma unroll
    for (int i = 0; i < 8; i++)
#pragma unroll
        for (int j = 0; j < 4; j++) acc[i][j] = 0ull;   // two packed 0.0f

    const float* Ap = A + (size_t)(m0 + arow) * DMODEL + acol;
    const float* Wp = W + (size_t)brow * N_COLS + n0 + bcol;
    const size_t w8 = (size_t)8 * N_COLS;

    // ---- prologue: stage 0 ----
    {
        float4 a0 = *(const float4*)(Ap);
        float4 a1 = *(const float4*)(Ap + 4);
        float4 b0 = *(const float4*)(Wp);
        float4 b1 = *(const float4*)(Wp + w8);
        As[0][acol + 0][arow] = a0.x; As[0][acol + 1][arow] = a0.y;
        As[0][acol + 2][arow] = a0.z; As[0][acol + 3][arow] = a0.w;
        As[0][acol + 4][arow] = a1.x; As[0][acol + 5][arow] = a1.y;
        As[0][acol + 6][arow] = a1.z; As[0][acol + 7][arow] = a1.w;
        *(float4*)&Bs[0][brow][bcol]     = b0;
        *(float4*)&Bs[0][brow + 8][bcol] = b1;
    }
    __syncthreads();

    for (int it = 0; it < 64; ++it) {          // K = 1024 / 16
        const int buf = it & 1;
        float4 na0, na1, nb0, nb1;
        const bool more = (it < 63);
        if (more) {
            const int k0 = (it + 1) * 16;
            na0 = *(const float4*)(Ap + k0);
            na1 = *(const float4*)(Ap + k0 + 4);
            nb0 = *(const float4*)(Wp + (size_t)k0 * N_COLS);
            nb1 = *(const float4*)(Wp + (size_t)k0 * N_COLS + w8);
        }

#pragma unroll
        for (int kk = 0; kk < 16; kk++) {
            float a[8];
            *(float4*)&a[0] = *(const float4*)&As[buf][kk][ty * 8];
            *(float4*)&a[4] = *(const float4*)&As[buf][kk][ty * 8 + 4];
            ulonglong2 bb0 = *(const ulonglong2*)&Bs[buf][kk][tx * 8];
            ulonglong2 bb1 = *(const ulonglong2*)&Bs[buf][kk][tx * 8 + 4];
            ull b2[4];
            b2[0] = bb0.x; b2[1] = bb0.y; b2[2] = bb1.x; b2[3] = bb1.y;
#pragma unroll
            for (int i = 0; i < 8; i++) {
                ull ai = pk2(a[i]);                 // alu-pipe pack, overlaps fma pipe
                fma2(acc[i][0], ai, b2[0]);
                fma2(acc[i][1], ai, b2[1]);
                fma2(acc[i][2], ai, b2[2]);
                fma2(acc[i][3], ai, b2[3]);
            }
        }

        if (more) {
            const int nb = buf ^ 1;
            As[nb][acol + 0][arow] = na0.x; As[nb][acol + 1][arow] = na0.y;
            As[nb][acol + 2][arow] = na0.z; As[nb][acol + 3][arow] = na0.w;
            As[nb][acol + 4][arow] = na1.x; As[nb][acol + 5][arow] = na1.y;
            As[nb][acol + 6][arow] = na1.z; As[nb][acol + 7][arow] = na1.w;
            *(float4*)&Bs[nb][brow][bcol]     = nb0;
            *(float4*)&Bs[nb][brow + 8][bcol] = nb1;
        }
        __syncthreads();
    }

    // ---- epilogue ----
    const int nbase = n0 + tx * 8;
    ull bp[4];
#pragma unroll
    for (int j = 0; j < 4; j++)
        bp[j] = pk2(bias[nbase + 2 * j], bias[nbase + 2 * j + 1]);
#pragma unroll
    for (int i = 0; i < 8; i++)
#pragma unroll
        for (int j = 0; j < 4; j++)
            acc[i][j] = add2(acc[i][j], bp[j]);

    if (MODE == 0) {
        // n -> (part, head, d). 8-wide chunk never crosses a 64 boundary.
        const int part = nbase >> 10;
        const int h    = (nbase & 1023) >> 6;
        const int d0   = nbase & 63;
        float* dst = (part == 0) ? g_q : (part == 1) ? g_k : g_v;
#pragma unroll
        for (int i = 0; i < 8; i++) {
            int m = m0 + ty * 8 + i;
            int b = m >> 11;          // S = 2048
            int s = m & 2047;
            float* p = dst + ((size_t)(b * NHEADS + h) * S_LEN + s) * DHEAD + d0;
            ulonglong2 v0; v0.x = acc[i][0]; v0.y = acc[i][1];
            ulonglong2 v1; v1.x = acc[i][2]; v1.y = acc[i][3];
            *(ulonglong2*)p       = v0;
            *(ulonglong2*)(p + 4) = v1;
        }
    } else {
#pragma unroll
        for (int i = 0; i < 8; i++) {
            int m = m0 + ty * 8 + i;
            float* p = out + (size_t)m * N_COLS + nbase;
            ulonglong2 v0; v0.x = acc[i][0]; v0.y = acc[i][1];
            ulonglong2 v1; v1.x = acc[i][2]; v1.y = acc[i][3];
            *(ulonglong2*)p       = v0;
            *(ulonglong2*)(p + 4) = v1;
        }
    }
}

// ---------------------------------------------------------------------------
// Windowed attention, flash-style online softmax, f32x2 in both GEMM loops.
// Block = (b,h) x 64-query tile, 256 threads (16x16).
// Key tiles of 32; query i attends keys j in [i, i+255] (anti-causal window).
// ---------------------------------------------------------------------------
__global__ __launch_bounds__(256, 4) void attn_kernel()
{
    __shared__ float Qt[64][64];   // [d][q] (transposed)
    __shared__ float Kt[64][32];   // [d][k] (transposed)
    __shared__ float Vs[32][64];   // [k][d]
    __shared__ float Ps[32][68];   // [k][q], padded stride 68

    const int tid = threadIdx.x;
    const int ty  = tid >> 4;      // 0..15 -> 4 query rows each
    const int tx  = tid & 15;      // 0..15 -> 2 key cols (scores) / 4 dv cols (PV)
    const int q0  = blockIdx.x * 64;
    const int bh  = blockIdx.y;
    const int h   = bh & 15;
    const int b   = bh >> 4;

    const float* __restrict__ Q = g_q + (size_t)bh * S_LEN * DHEAD;
    const float* __restrict__ K = g_k + (size_t)bh * S_LEN * DHEAD;
    const float* __restrict__ V = g_v + (size_t)bh * S_LEN * DHEAD;

    // Load Q tile (transposed into smem); 4 float4 per thread
    {
        int q  = tid >> 2;              // 0..63
        int d0 = (tid & 3) << 4;        // 0,16,32,48
        const float* src = Q + (size_t)(q0 + q) * DHEAD + d0;
#pragma unroll
        for (int i = 0; i < 4; i++) {
            float4 v = *(const float4*)(src + 4 * i);
            Qt[d0 + 4 * i + 0][q] = v.x;
            Qt[d0 + 4 * i + 1][q] = v.y;
            Qt[d0 + 4 * i + 2][q] = v.z;
            Qt[d0 + 4 * i + 3][q] = v.w;
        }
    }

    ull O2[4][2];                       // 4 q-rows x 2 packed d-pairs (=4 dv cols)
    float mrow[4], lrow[4];
#pragma unroll
    for (int i = 0; i < 4; i++) {
        mrow[i] = -1e30f;
        lrow[i] = 0.f;
        O2[i][0] = 0ull; O2[i][1] = 0ull;
    }
    const int qrow0 = q0 + ty * 4;

    for (int t = 0; t < 10; t++) {       // covers keys [q0, q0+319]
        const int kt0 = q0 + t * 32;
        if (kt0 >= S_LEN) break;

        __syncthreads();   // previous tile's readers done with Kt/Vs/Ps

        // Load K (transposed) and V tiles: 32 keys x 64 dims, 8 floats/thread each
        {
            int kk = tid >> 3;              // 0..31
            int d0 = (tid & 7) << 3;        // 0..56
            int krow = kt0 + kk;
            if (krow > S_LEN - 1) krow = S_LEN - 1;   // clamp; masked below
            const float* ks = K + (size_t)krow * DHEAD + d0;
            float4 k0v = *(const float4*)ks;
            float4 k1v = *(const float4*)(ks + 4);
            Kt[d0 + 0][kk] = k0v.x; Kt[d0 + 1][kk] = k0v.y;
            Kt[d0 + 2][kk] = k0v.z; Kt[d0 + 3][kk] = k0v.w;
            Kt[d0 + 4][kk] = k1v.x; Kt[d0 + 5][kk] = k1v.y;
            Kt[d0 + 6][kk] = k1v.z; Kt[d0 + 7][kk] = k1v.w;
            const float* vsrc = V + (size_t)krow * DHEAD + d0;
            *(float4*)&Vs[kk][d0]     = *(const float4*)vsrc;
            *(float4*)&Vs[kk][d0 + 4] = *(const float4*)(vsrc + 4);
        }
        __syncthreads();

        // Scores: 4q x 2k per thread (packed pair along k), contraction over 64 dims
        ull sc2[4];
        sc2[0] = 0ull; sc2[1] = 0ull; sc2[2] = 0ull; sc2[3] = 0ull;
#pragma unroll 16
        for (int d = 0; d < 64; d++) {
            float4 a = *(const float4*)&Qt[d][ty * 4];
            ull k2   = *(const ull*)&Kt[d][tx * 2];    // 8B-aligned pair
            fma2(sc2[0], pk2(a.x), k2);
            fma2(sc2[1], pk2(a.y), k2);
            fma2(sc2[2], pk2(a.z), k2);
            fma2(sc2[3], pk2(a.w), k2);
        }
        float sc[4][2];
#pragma unroll
        for (int i = 0; i < 4; i++) upk2(sc2[i], sc[i][0], sc[i][1]);

        // Mask + scale
#pragma unroll
        for (int i = 0; i < 4; i++) {
            int qrow = qrow0 + i;
#pragma unroll
            for (int j = 0; j < 2; j++) {
                int krow = kt0 + tx * 2 + j;
                bool keep = (krow >= qrow) && (krow <= qrow + (WIN - 1)) && (krow < S_LEN);
                sc[i][j] = keep ? sc[i][j] * ATT_SCALE : -INFINITY;
            }
        }

        // Online softmax update (row reduce across the 16 tx lanes)
#pragma unroll
        for (int i = 0; i < 4; i++) {
            float tmax = fmaxf(sc[i][0], sc[i][1]);
#pragma unroll
            for (int o = 1; o < 16; o <<= 1)
                tmax = fmaxf(tmax, __shfl_xor_sync(0xffffffffu, tmax, o));
            float nm  = fmaxf(mrow[i], tmax);
            float fac = __expf(mrow[i] - nm);
            mrow[i]   = nm;
            float p0 = __expf(sc[i][0] - nm);
            float p1 = __expf(sc[i][1] - nm);
            sc[i][0] = p0; sc[i][1] = p1;
            float tsum = p0 + p1;
#pragma unroll
            for (int o = 1; o < 16; o <<= 1)
                tsum += __shfl_xor_sync(0xffffffffu, tsum, o);
            lrow[i] = lrow[i] * fac + tsum;
            ull f2 = pk2(fac);
            O2[i][0] = mul2(O2[i][0], f2);
            O2[i][1] = mul2(O2[i][1], f2);
        }

        // Stage P into smem as [k][q]
#pragma unroll
        for (int i = 0; i < 4; i++) {
            Ps[tx * 2 + 0][ty * 4 + i] = sc[i][0];
            Ps[tx * 2 + 1][ty * 4 + i] = sc[i][1];
        }
        __syncthreads();

        // O += P @ V : 4q x 4d per thread (packed pairs along d), 32 keys
#pragma unroll 8
        for (int k = 0; k < 32; k++) {
            float4 pv     = *(const float4*)&Ps[k][ty * 4];
            ulonglong2 vv = *(const ulonglong2*)&Vs[k][tx * 4];
            ull p0 = pk2(pv.x), p1 = pk2(pv.y), p2 = pk2(pv.z), p3 = pk2(pv.w);
            fma2(O2[0][0], p0, vv.x); fma2(O2[0][1], p0, vv.y);
            fma2(O2[1][0], p1, vv.x); fma2(O2[1][1], p1, vv.y);
            fma2(O2[2][0], p2, vv.x); fma2(O2[2][1], p2, vv.y);
            fma2(O2[3][0], p3, vv.x); fma2(O2[3][1], p3, vv.y);
        }
    }

    // Finalize: divide by l, write ctx[b, s, h*64 + dv]
#pragma unroll
    for (int i = 0; i < 4; i++) {
        float inv = 1.0f / lrow[i];
        ull i2 = pk2(inv);
        int srow = qrow0 + i;
        float* dst = g_ctx + ((size_t)(b * S_LEN + srow)) * DMODEL + h * 64 + tx * 4;
        ulonglong2 r; r.x = mul2(O2[i][0], i2); r.y = mul2(O2[i][1], i2);
        *(ulonglong2*)dst = r;
    }
}

// ---------------------------------------------------------------------------
extern "C" void kernel_launch(void* const* d_in, const int* in_sizes, int n_in,
                              void* d_out, int out_size)
{
    const float* x    = (const float*)d_in[0];   // [2,2048,1024]
    const float* Wqkv = (const float*)d_in[1];   // [1024,3072]
    const float* bqkv = (const float*)d_in[2];   // [3072]
    const float* Wout = (const float*)d_in[3];   // [1024,1024]
    const float* bout = (const float*)d_in[4];   // [1024]
    float* out = (float*)d_out;                  // [2,2048,1024]
    (void)in_sizes; (void)n_in; (void)out_size;

    dim3 blk(256);
    // QKV projection: M=4096, N=3072, K=1024 -> scatter to g_q/g_k/g_v
    sgemm_kernel<3072, 0><<<dim3(3072 / 128, MROWS / 128), blk>>>(x, Wqkv, bqkv, nullptr);
    // Windowed attention -> g_ctx
    attn_kernel<<<dim3(S_LEN / 64, BH), blk>>>();
    // Output projection: M=4096, N=1024, K=1024
    sgemm_kernel<1024, 1><<<dim3(1024 / 128, MROWS / 128), blk>>>(nullptr, Wout, bout, out);
}

// round 7
// speedup vs baseline: 1.9493x; 1.7656x over previous
#include <cuda_runtime.h>
#include <cuda_bf16.h>
#include <math.h>
#include <stdint.h>

#define S_LEN 2048
#define DMODEL 1024
#define NHEADS 16
#define DHEAD 64
#define WIN 256
#define BATCH 2
#define BH (BATCH * NHEADS)
#define MROWS (BATCH * S_LEN)
#define KEXP (3 * DMODEL)          // expanded K for 3-term bf16 split
#define ATT_SCALE 0.125f

typedef unsigned long long ull;

// ---- packed f32x2 helpers (attention kernel) ----
__device__ __forceinline__ ull pk2(float x) {
    ull r; asm("mov.b64 %0, {%1, %1};" : "=l"(r) : "f"(x)); return r;
}
__device__ __forceinline__ void upk2(ull v, float& x, float& y) {
    asm("mov.b64 {%0, %1}, %2;" : "=f"(x), "=f"(y) : "l"(v));
}
__device__ __forceinline__ void fma2(ull& d, ull a, ull b) {
    asm("fma.rn.f32x2 %0, %1, %2, %0;" : "+l"(d) : "l"(a), "l"(b));
}
__device__ __forceinline__ ull mul2(ull a, ull b) {
    ull r; asm("mul.rn.f32x2 %0, %1, %2;" : "=l"(r) : "l"(a), "l"(b)); return r;
}

// ---- mma.sync / ldmatrix / cp.async helpers (baseline PTX, no sm_103a gating) ----
__device__ __forceinline__ uint32_t smem_u32(const void* p) {
    uint32_t a;
    asm("{ .reg .u64 t; cvta.to.shared.u64 t, %1; cvt.u32.u64 %0, t; }" : "=r"(a) : "l"(p));
    return a;
}
__device__ __forceinline__ void ldsm4(uint32_t* r, uint32_t addr) {
    asm volatile("ldmatrix.sync.aligned.m8n8.x4.shared.b16 {%0,%1,%2,%3}, [%4];"
                 : "=r"(r[0]), "=r"(r[1]), "=r"(r[2]), "=r"(r[3]) : "r"(addr));
}
__device__ __forceinline__ void mma16816(float* d, const uint32_t* a, const uint32_t* b) {
    asm volatile("mma.sync.aligned.m16n8k16.row.col.f32.bf16.bf16.f32 "
        "{%0,%1,%2,%3}, {%4,%5,%6,%7}, {%8,%9}, {%0,%1,%2,%3};"
        : "+f"(d[0]), "+f"(d[1]), "+f"(d[2]), "+f"(d[3])
        : "r"(a[0]), "r"(a[1]), "r"(a[2]), "r"(a[3]), "r"(b[0]), "r"(b[1]));
}
__device__ __forceinline__ void cpa16(uint32_t dst, const void* src) {
    asm volatile("cp.async.cg.shared.global [%0], [%1], 16;" :: "r"(dst), "l"(src));
}
#define CP_COMMIT() asm volatile("cp.async.commit_group;" ::: "memory")
#define CP_WAIT1()  asm volatile("cp.async.wait_group 1;" ::: "memory")

// Scratch (allocation-free rule: __device__ globals)
__device__ float g_q[BH * S_LEN * DHEAD];
__device__ float g_k[BH * S_LEN * DHEAD];
__device__ float g_v[BH * S_LEN * DHEAD];
__device__ __nv_bfloat16 g_xexp[(size_t)MROWS * KEXP];        // [4096][3072] hi|lo|hi
__device__ __nv_bfloat16 g_cexp[(size_t)MROWS * KEXP];        // attention out, hi|lo|hi
__device__ __nv_bfloat16 g_wqexp[(size_t)(3 * DMODEL) * KEXP];// W_qkv^T [3072][3072] hi|hi|lo
__device__ __nv_bfloat16 g_woexp[(size_t)DMODEL * KEXP];      // W_out^T [1024][3072] hi|hi|lo

__device__ __forceinline__ void bf_split(float v, __nv_bfloat16& hi, __nv_bfloat16& lo) {
    hi = __float2bfloat16_rn(v);
    lo = __float2bfloat16_rn(v - __bfloat162float(hi));
}

// ---------------------------------------------------------------------------
// Split x [4096][1024] f32 -> g_xexp [4096][3072] bf16 as [hi | lo | hi]
// ---------------------------------------------------------------------------
__global__ __launch_bounds__(256) void split_x_kernel(const float* __restrict__ src)
{
    int idx = blockIdx.x * 256 + threadIdx.x;      // one float4 per thread
    int m = idx >> 8;
    int c = (idx & 255) << 2;
    float4 v = *(const float4*)(src + (size_t)m * DMODEL + c);
    __nv_bfloat16 h[4], l[4];
    bf_split(v.x, h[0], l[0]); bf_split(v.y, h[1], l[1]);
    bf_split(v.z, h[2], l[2]); bf_split(v.w, h[3], l[3]);
    __nv_bfloat16* row = g_xexp + (size_t)m * KEXP;
    __nv_bfloat162 h01 = {h[0], h[1]}, h23 = {h[2], h[3]};
    __nv_bfloat162 l01 = {l[0], l[1]}, l23 = {l[2], l[3]};
    *(__nv_bfloat162*)(row + c)            = h01; *(__nv_bfloat162*)(row + c + 2)        = h23;
    *(__nv_bfloat162*)(row + 1024 + c)     = l01; *(__nv_bfloat162*)(row + 1024 + c + 2) = l23;
    *(__nv_bfloat162*)(row + 2048 + c)     = h01; *(__nv_bfloat162*)(row + 2048 + c + 2) = h23;
}

// ---------------------------------------------------------------------------
// Transpose + split weights: W [1024][NC] f32 -> dst [NC][3072] bf16 [hi|hi|lo]
// ---------------------------------------------------------------------------
template <int WHICH>
__global__ __launch_bounds__(256) void wsplit_kernel(const float* __restrict__ src, int NC)
{
    __shared__ float tile[32][33];
    int n0 = blockIdx.x * 32, k0 = blockIdx.y * 32;
    int tx = threadIdx.x, ty = threadIdx.y;   // 32 x 8
#pragma unroll
    for (int i = 0; i < 32; i += 8)
        tile[ty + i][tx] = src[(size_t)(k0 + ty + i) * NC + n0 + tx];
    __syncthreads();
    __nv_bfloat16* dst = WHICH ? g_woexp : g_wqexp;
#pragma unroll
    for (int i = 0; i < 32; i += 8) {
        float v = tile[tx][ty + i];            // = src[k0+tx][n0+ty+i]
        int n = n0 + ty + i, k = k0 + tx;
        __nv_bfloat16 hi, lo; bf_split(v, hi, lo);
        __nv_bfloat16* r = dst + (size_t)n * KEXP;
        r[k] = hi; r[1024 + k] = hi; r[2048 + k] = lo;
    }
}

// ---------------------------------------------------------------------------
// bf16 mma.sync GEMM: C[M,N] = Aexp[M,3072] . Bexp[N,3072]^T + bias
// 128x128x32 tiles, 3-stage cp.async pipeline, XOR-swizzled smem + ldmatrix.
// 256 threads = 8 warps (4M x 2N); warp tile 32x64; 64 f32 acc/thread.
// MODE 0: A=g_xexp B=g_wqexp, scatter into g_q/g_k/g_v.  MODE 1: A=g_cexp B=g_woexp -> out.
// ---------------------------------------------------------------------------
#define BM 128
#define BN 128
#define BK 32
#define NIT (KEXP / BK)   // 96
#define STG_A 8192        // bytes per stage (128*32*2)

template <int MODE>
__global__ __launch_bounds__(256, 2) void mma_gemm_kernel(
    const float* __restrict__ bias, float* __restrict__ out)
{
    __shared__ __nv_bfloat16 sA[3][BM * BK];
    __shared__ __nv_bfloat16 sB[3][BN * BK];

    const __nv_bfloat16* __restrict__ Aexp = MODE ? g_cexp : g_xexp;
    const __nv_bfloat16* __restrict__ Bexp = MODE ? g_woexp : g_wqexp;

    const int tid = threadIdx.x;
    const int wid = tid >> 5, lid = tid & 31;
    const int m0 = blockIdx.y * BM, n0 = blockIdx.x * BN;
    const int wm = wid & 3, wn = wid >> 2;

    // ---- global->smem load mapping: thread t loads 32B of A and 32B of B per iter
    const int ldrow = tid >> 1;                 // 0..127
    const int ldc0  = (tid & 1) << 1;           // chunk 0 or 2 (16B chunks)
    const int ldsw  = (ldrow >> 1) & 3;         // swizzle
    const __nv_bfloat16* gA = Aexp + (size_t)(m0 + ldrow) * KEXP + (ldc0 << 3);
    const __nv_bfloat16* gB = Bexp + (size_t)(n0 + ldrow) * KEXP + (ldc0 << 3);
    const uint32_t sAb = smem_u32(&sA[0][0]);
    const uint32_t sBb = smem_u32(&sB[0][0]);
    const uint32_t dA0 = sAb + (uint32_t)(ldrow * 32 + ((ldc0 ^ ldsw) << 3)) * 2;
    const uint32_t dA1 = sAb + (uint32_t)(ldrow * 32 + (((ldc0 + 1) ^ ldsw) << 3)) * 2;
    const uint32_t dB0 = sBb + (uint32_t)(ldrow * 32 + ((ldc0 ^ ldsw) << 3)) * 2;
    const uint32_t dB1 = sBb + (uint32_t)(ldrow * 32 + (((ldc0 + 1) ^ ldsw) << 3)) * 2;

    // ---- ldmatrix per-lane base addresses (k16=0), XOR (k16<<5) to step k
    uint32_t aAddr[2];
#pragma unroll
    for (int mi = 0; mi < 2; mi++) {
        int r = wm * 32 + mi * 16 + (lid & 15);
        int h = lid >> 4;                        // k-chunk low bit
        int e0 = h ^ ((r >> 1) & 3);
        aAddr[mi] = sAb + (uint32_t)(r * 64 + (e0 << 4));
    }
    uint32_t bAddr[4];
#pragma unroll
    for (int ni = 0; ni < 4; ni++) {
        int r = wn * 64 + ni * 16 + ((lid >> 4) << 3) + (lid & 7);
        int h = (lid >> 3) & 1;
        int e0 = h ^ ((r >> 1) & 3);
        bAddr[ni] = sBb + (uint32_t)(r * 64 + (e0 << 4));
    }

    float acc[2][8][4];
#pragma unroll
    for (int i = 0; i < 2; i++)
#pragma unroll
        for (int j = 0; j < 8; j++)
#pragma unroll
            for (int k = 0; k < 4; k++) acc[i][j][k] = 0.f;

    // ---- prologue: stages 0,1
#pragma unroll
    for (int s = 0; s < 2; s++) {
        const __nv_bfloat16* a = gA + s * BK;
        const __nv_bfloat16* b = gB + s * BK;
        uint32_t so = s * STG_A;
        cpa16(dA0 + so, a); cpa16(dA1 + so, a + 8);
        cpa16(dB0 + so, b); cpa16(dB1 + so, b + 8);
        CP_COMMIT();
    }

    int stage = 0, nstage = 2;
    for (int kt = 0; kt < NIT; ++kt) {
        CP_WAIT1();
        __syncthreads();

        if (kt + 2 < NIT) {
            const __nv_bfloat16* a = gA + (kt + 2) * BK;
            const __nv_bfloat16* b = gB + (kt + 2) * BK;
            uint32_t so = nstage * STG_A;
            cpa16(dA0 + so, a); cpa16(dA1 + so, a + 8);
            cpa16(dB0 + so, b); cpa16(dB1 + so, b + 8);
        }
        CP_COMMIT();

        const uint32_t so = stage * STG_A;
#pragma unroll
        for (int k16 = 0; k16 < 2; k16++) {
            const uint32_t kx = (uint32_t)(k16 << 5);
            uint32_t ar[2][4], br[4][4];
            ldsm4(ar[0], (aAddr[0] + so) ^ kx);
            ldsm4(ar[1], (aAddr[1] + so) ^ kx);
#pragma unroll
            for (int ni = 0; ni < 4; ni++)
                ldsm4(br[ni], (bAddr[ni] + so) ^ kx);
#pragma unroll
            for (int mi = 0; mi < 2; mi++)
#pragma unroll
                for (int n8 = 0; n8 < 8; n8++)
                    mma16816(acc[mi][n8], ar[mi], &br[n8 >> 1][(n8 & 1) << 1]);
        }
        stage = stage == 2 ? 0 : stage + 1;
        nstage = nstage == 2 ? 0 : nstage + 1;
    }

    // ---- epilogue: acc fragment (row = l>>2 [+8], col = (l&3)*2 [+1])
    const int row_l = lid >> 2;
    const int col_l = (lid & 3) << 1;
#pragma unroll
    for (int ni = 0; ni < 8; ni++) {
        const int c = n0 + wn * 64 + ni * 8 + col_l;
        const float bx = bias[c], by = bias[c + 1];
#pragma unroll
        for (int mi = 0; mi < 2; mi++) {
            const int r = m0 + wm * 32 + mi * 16 + row_l;
            float2 v0 = make_float2(acc[mi][ni][0] + bx, acc[mi][ni][1] + by);
            float2 v1 = make_float2(acc[mi][ni][2] + bx, acc[mi][ni][3] + by);
            if (MODE == 0) {
                const int part = c >> 10;
                const int h    = (c & 1023) >> 6;
                const int d    = c & 63;
                const int bb   = r >> 11;        // S=2048, 128-aligned tiles: r,r+8 same batch
                const int s    = r & 2047;
                float* dst = (part == 0) ? g_q : (part == 1) ? g_k : g_v;
                float* p = dst + ((size_t)(bb * NHEADS + h) * S_LEN + s) * DHEAD + d;
                *(float2*)p                = v0;
                *(float2*)(p + 8 * DHEAD)  = v1;   // row r+8
            } else {
                float* p = out + (size_t)r * DMODEL + c;
                *(float2*)p                = v0;
                *(float2*)(p + 8 * DMODEL) = v1;
            }
        }
    }
}

// ---------------------------------------------------------------------------
// Windowed attention (f32x2 FFMA2), epilogue writes bf16 split [hi|lo|hi]
// ---------------------------------------------------------------------------
__global__ __launch_bounds__(256, 4) void attn_kernel()
{
    __shared__ float Qt[64][64];
    __shared__ float Kt[64][32];
    __shared__ float Vs[32][64];
    __shared__ float Ps[32][68];

    const int tid = threadIdx.x;
    const int ty  = tid >> 4;
    const int tx  = tid & 15;
    const int q0  = blockIdx.x * 64;
    const int bh  = blockIdx.y;
    const int h   = bh & 15;
    const int b   = bh >> 4;

    const float* __restrict__ Q = g_q + (size_t)bh * S_LEN * DHEAD;
    const float* __restrict__ K = g_k + (size_t)bh * S_LEN * DHEAD;
    const float* __restrict__ V = g_v + (size_t)bh * S_LEN * DHEAD;

    {
        int q  = tid >> 2;
        int d0 = (tid & 3) << 4;
        const float* src = Q + (size_t)(q0 + q) * DHEAD + d0;
#pragma unroll
        for (int i = 0; i < 4; i++) {
            float4 v = *(const float4*)(src + 4 * i);
            Qt[d0 + 4 * i + 0][q] = v.x;
            Qt[d0 + 4 * i + 1][q] = v.y;
            Qt[d0 + 4 * i + 2][q] = v.z;
            Qt[d0 + 4 * i + 3][q] = v.w;
        }
    }

    ull O2[4][2];
    float mrow[4], lrow[4];
#pragma unroll
    for (int i = 0; i < 4; i++) {
        mrow[i] = -1e30f; lrow[i] = 0.f;
        O2[i][0] = 0ull; O2[i][1] = 0ull;
    }
    const int qrow0 = q0 + ty * 4;

    for (int t = 0; t < 10; t++) {
        const int kt0 = q0 + t * 32;
        if (kt0 >= S_LEN) break;
        __syncthreads();
        {
            int kk = tid >> 3;
            int d0 = (tid & 7) << 3;
            int krow = kt0 + kk;
            if (krow > S_LEN - 1) krow = S_LEN - 1;
            const float* ks = K + (size_t)krow * DHEAD + d0;
            float4 k0v = *(const float4*)ks;
            float4 k1v = *(const float4*)(ks + 4);
            Kt[d0 + 0][kk] = k0v.x; Kt[d0 + 1][kk] = k0v.y;
            Kt[d0 + 2][kk] = k0v.z; Kt[d0 + 3][kk] = k0v.w;
            Kt[d0 + 4][kk] = k1v.x; Kt[d0 + 5][kk] = k1v.y;
            Kt[d0 + 6][kk] = k1v.z; Kt[d0 + 7][kk] = k1v.w;
            const float* vsrc = V + (size_t)krow * DHEAD + d0;
            *(float4*)&Vs[kk][d0]     = *(const float4*)vsrc;
            *(float4*)&Vs[kk][d0 + 4] = *(const float4*)(vsrc + 4);
        }
        __syncthreads();

        ull sc2[4];
        sc2[0] = 0ull; sc2[1] = 0ull; sc2[2] = 0ull; sc2[3] = 0ull;
#pragma unroll 16
        for (int d = 0; d < 64; d++) {
            float4 a = *(const float4*)&Qt[d][ty * 4];
            ull k2   = *(const ull*)&Kt[d][tx * 2];
            fma2(sc2[0], pk2(a.x), k2);
            fma2(sc2[1], pk2(a.y), k2);
            fma2(sc2[2], pk2(a.z), k2);
            fma2(sc2[3], pk2(a.w), k2);
        }
        float sc[4][2];
#pragma unroll
        for (int i = 0; i < 4; i++) upk2(sc2[i], sc[i][0], sc[i][1]);

#pragma unroll
        for (int i = 0; i < 4; i++) {
            int qrow = qrow0 + i;
#pragma unroll
            for (int j = 0; j < 2; j++) {
                int krow = kt0 + tx * 2 + j;
                bool keep = (krow >= qrow) && (krow <= qrow + (WIN - 1)) && (krow < S_LEN);
                sc[i][j] = keep ? sc[i][j] * ATT_SCALE : -INFINITY;
            }
        }

#pragma unroll
        for (int i = 0; i < 4; i++) {
            float tmax = fmaxf(sc[i][0], sc[i][1]);
#pragma unroll
            for (int o = 1; o < 16; o <<= 1)
                tmax = fmaxf(tmax, __shfl_xor_sync(0xffffffffu, tmax, o));
            float nm  = fmaxf(mrow[i], tmax);
            float fac = __expf(mrow[i] - nm);
            mrow[i]   = nm;
            float p0 = __expf(sc[i][0] - nm);
            float p1 = __expf(sc[i][1] - nm);
            sc[i][0] = p0; sc[i][1] = p1;
            float tsum = p0 + p1;
#pragma unroll
            for (int o = 1; o < 16; o <<= 1)
                tsum += __shfl_xor_sync(0xffffffffu, tsum, o);
            lrow[i] = lrow[i] * fac + tsum;
            ull f2 = pk2(fac);
            O2[i][0] = mul2(O2[i][0], f2);
            O2[i][1] = mul2(O2[i][1], f2);
        }

#pragma unroll
        for (int i = 0; i < 4; i++) {
            Ps[tx * 2 + 0][ty * 4 + i] = sc[i][0];
            Ps[tx * 2 + 1][ty * 4 + i] = sc[i][1];
        }
        __syncthreads();

#pragma unroll 8
        for (int k = 0; k < 32; k++) {
            float4 pv     = *(const float4*)&Ps[k][ty * 4];
            ulonglong2 vv = *(const ulonglong2*)&Vs[k][tx * 4];
            ull p0 = pk2(pv.x), p1 = pk2(pv.y), p2 = pk2(pv.z), p3 = pk2(pv.w);
            fma2(O2[0][0], p0, vv.x); fma2(O2[0][1], p0, vv.y);
            fma2(O2[1][0], p1, vv.x); fma2(O2[1][1], p1, vv.y);
            fma2(O2[2][0], p2, vv.x); fma2(O2[2][1], p2, vv.y);
            fma2(O2[3][0], p3, vv.x); fma2(O2[3][1], p3, vv.y);
        }
    }

    // Finalize: divide by l, write split bf16 [hi|lo|hi] into g_cexp
#pragma unroll
    for (int i = 0; i < 4; i++) {
        float inv = 1.0f / lrow[i];
        float f0, f1, f2v, f3v;
        upk2(O2[i][0], f0, f1); upk2(O2[i][1], f2v, f3v);
        f0 *= inv; f1 *= inv; f2v *= inv; f3v *= inv;
        __nv_bfloat16 h0, h1, h2, h3, l0, l1, l2, l3;
        bf_split(f0, h0, l0); bf_split(f1, h1, l1);
        bf_split(f2v, h2, l2); bf_split(f3v, h3, l3);
        int m = b * S_LEN + qrow0 + i;
        __nv_bfloat16* dst = g_cexp + (size_t)m * KEXP + h * 64 + tx * 4;
        __nv_bfloat162 h01 = {h0, h1}, h23 = {h2, h3};
        __nv_bfloat162 l01 = {l0, l1}, l23 = {l2, l3};
        *(__nv_bfloat162*)(dst)              = h01; *(__nv_bfloat162*)(dst + 2)        = h23;
        *(__nv_bfloat162*)(dst + 1024)       = l01; *(__nv_bfloat162*)(dst + 1026)     = l23;
        *(__nv_bfloat162*)(dst + 2048)       = h01; *(__nv_bfloat162*)(dst + 2050)     = h23;
    }
}

// ---------------------------------------------------------------------------
extern "C" void kernel_launch(void* const* d_in, const int* in_sizes, int n_in,
                              void* d_out, int out_size)
{
    const float* x    = (const float*)d_in[0];
    const float* Wqkv = (const float*)d_in[1];
    const float* bqkv = (const float*)d_in[2];
    const float* Wout = (const float*)d_in[3];
    const float* bout = (const float*)d_in[4];
    float* out = (float*)d_out;
    (void)in_sizes; (void)n_in; (void)out_size;

    // Prep: split x, transpose+split weights (bf16 hi/lo expansion)
    split_x_kernel<<<MROWS * DMODEL / 4 / 256, 256>>>(x);
    wsplit_kernel<0><<<dim3(3 * DMODEL / 32, DMODEL / 32), dim3(32, 8)>>>(Wqkv, 3 * DMODEL);
    wsplit_kernel<1><<<dim3(DMODEL / 32, DMODEL / 32), dim3(32, 8)>>>(Wout, DMODEL);

    // QKV projection (bf16 mma.sync, 3-term split): M=4096, N=3072
    mma_gemm_kernel<0><<<dim3(3 * DMODEL / BN, MROWS / BM), 256>>>(bqkv, nullptr);
    // Windowed attention -> g_cexp (pre-split)
    attn_kernel<<<dim3(S_LEN / 64, BH), 256>>>();
    // Output projection: M=4096, N=1024
    mma_gemm_kernel<1><<<dim3(DMODEL / BN, MROWS / BM), 256>>>(bout, out);
}

// round 8
// speedup vs baseline: 2.2501x; 1.1543x over previous
#include <cuda_runtime.h>
#include <cuda_fp16.h>
#include <math.h>
#include <stdint.h>

#define S_LEN 2048
#define DMODEL 1024
#define NHEADS 16
#define DHEAD 64
#define WIN 256
#define BATCH 2
#define BH (BATCH * NHEADS)
#define MROWS (BATCH * S_LEN)
#define KD 1024
#define ATT_SCALE 0.125f

typedef unsigned long long ull;

// ---- packed f32x2 helpers (attention kernel) ----
__device__ __forceinline__ ull pk2(float x) {
    ull r; asm("mov.b64 %0, {%1, %1};" : "=l"(r) : "f"(x)); return r;
}
__device__ __forceinline__ void upk2(ull v, float& x, float& y) {
    asm("mov.b64 {%0, %1}, %2;" : "=f"(x), "=f"(y) : "l"(v));
}
__device__ __forceinline__ void fma2(ull& d, ull a, ull b) {
    asm("fma.rn.f32x2 %0, %1, %2, %0;" : "+l"(d) : "l"(a), "l"(b));
}
__device__ __forceinline__ ull mul2(ull a, ull b) {
    ull r; asm("mul.rn.f32x2 %0, %1, %2;" : "=l"(r) : "l"(a), "l"(b)); return r;
}

// ---- mma.sync / ldmatrix / cp.async helpers (baseline PTX) ----
__device__ __forceinline__ uint32_t smem_u32(const void* p) {
    uint32_t a;
    asm("{ .reg .u64 t; cvta.to.shared.u64 t, %1; cvt.u32.u64 %0, t; }" : "=r"(a) : "l"(p));
    return a;
}
__device__ __forceinline__ void ldsm4(uint32_t* r, uint32_t addr) {
    asm volatile("ldmatrix.sync.aligned.m8n8.x4.shared.b16 {%0,%1,%2,%3}, [%4];"
                 : "=r"(r[0]), "=r"(r[1]), "=r"(r[2]), "=r"(r[3]) : "r"(addr));
}
__device__ __forceinline__ void mma16816(float* d, const uint32_t* a, const uint32_t* b) {
    asm volatile("mma.sync.aligned.m16n8k16.row.col.f32.f16.f16.f32 "
        "{%0,%1,%2,%3}, {%4,%5,%6,%7}, {%8,%9}, {%0,%1,%2,%3};"
        : "+f"(d[0]), "+f"(d[1]), "+f"(d[2]), "+f"(d[3])
        : "r"(a[0]), "r"(a[1]), "r"(a[2]), "r"(a[3]), "r"(b[0]), "r"(b[1]));
}
__device__ __forceinline__ void cpa16(uint32_t dst, const void* src) {
    asm volatile("cp.async.cg.shared.global [%0], [%1], 16;" :: "r"(dst), "l"(src));
}
#define CP_COMMIT() asm volatile("cp.async.commit_group;" ::: "memory")
#define CP_WAIT1()  asm volatile("cp.async.wait_group 1;" ::: "memory")

// Scratch (allocation-free rule: __device__ globals)
__device__ float g_q[BH * S_LEN * DHEAD];
__device__ float g_k[BH * S_LEN * DHEAD];
__device__ float g_v[BH * S_LEN * DHEAD];
__device__ __half g_xh[(size_t)MROWS * KD];           // fp16 hi of x
__device__ __half g_xl[(size_t)MROWS * KD];           // fp16 lo of x
__device__ __half g_ch[(size_t)MROWS * KD];           // fp16 hi of attention out
__device__ __half g_cl[(size_t)MROWS * KD];           // fp16 lo
__device__ __half g_wqh[(size_t)(3 * DMODEL) * KD];   // W_qkv^T fp16 hi [3072][1024]
__device__ __half g_woh[(size_t)DMODEL * KD];         // W_out^T fp16 hi [1024][1024]

__device__ __forceinline__ void h_split(float v, __half& hi, __half& lo) {
    hi = __float2half_rn(v);
    lo = __float2half_rn(v - __half2float(hi));
}

// ---------------------------------------------------------------------------
// Split x [4096][1024] f32 -> g_xh, g_xl fp16
// ---------------------------------------------------------------------------
__global__ __launch_bounds__(256) void split_x_kernel(const float* __restrict__ src)
{
    int idx = blockIdx.x * 256 + threadIdx.x;      // one float4 per thread
    int m = idx >> 8;
    int c = (idx & 255) << 2;
    float4 v = *(const float4*)(src + (size_t)m * KD + c);
    __half h[4], l[4];
    h_split(v.x, h[0], l[0]); h_split(v.y, h[1], l[1]);
    h_split(v.z, h[2], l[2]); h_split(v.w, h[3], l[3]);
    size_t o = (size_t)m * KD + c;
    *(__half2*)(g_xh + o)     = __half2{h[0], h[1]};
    *(__half2*)(g_xh + o + 2) = __half2{h[2], h[3]};
    *(__half2*)(g_xl + o)     = __half2{l[0], l[1]};
    *(__half2*)(g_xl + o + 2) = __half2{l[2], l[3]};
}

// ---------------------------------------------------------------------------
// Transpose + fp16 convert weights: W [1024][NC] f32 -> dst [NC][1024] fp16 hi
// ---------------------------------------------------------------------------
template <int WHICH>
__global__ __launch_bounds__(256) void wsplit_kernel(const float* __restrict__ src, int NC)
{
    __shared__ float tile[32][33];
    int n0 = blockIdx.x * 32, k0 = blockIdx.y * 32;
    int tx = threadIdx.x, ty = threadIdx.y;   // 32 x 8
#pragma unroll
    for (int i = 0; i < 32; i += 8)
        tile[ty + i][tx] = src[(size_t)(k0 + ty + i) * NC + n0 + tx];
    __syncthreads();
    __half* dst = WHICH ? g_woh : g_wqh;
#pragma unroll
    for (int i = 0; i < 32; i += 8) {
        float v = tile[tx][ty + i];            // = src[k0+tx][n0+ty+i]
        int n = n0 + ty + i, k = k0 + tx;
        dst[(size_t)n * KD + k] = __float2half_rn(v);
    }
}

// ---------------------------------------------------------------------------
// fp16 mma.sync GEMM with 2-term split, shared-B:
//   C[M,N] = (Ah + Al)[M,1024] . Bh[N,1024]^T + bias
// 128x128x32 CTA tiles; A smem stage holds hi rows [0,128) and lo rows [128,256);
// B fragments loaded once per k16 and reused for hi and lo MMAs.
// 3-stage cp.async pipeline, 72KB dynamic smem, 8 warps (4M x 2N), 64 f32 acc.
// MODE 0: A=g_xh/g_xl, B=g_wqh, scatter -> g_q/g_k/g_v.  MODE 1: A=g_ch/g_cl, B=g_woh -> out.
// ---------------------------------------------------------------------------
#define BM 128
#define BN 128
#define BK 32
#define NIT 32                 // 1024 / 32
#define SA_BYTES 16384         // 256 rows x 64B
#define SB_BYTES 8192          // 128 rows x 64B
#define STG_BYTES (SA_BYTES + SB_BYTES)   // 24576
#define SMEM_DYN (3 * STG_BYTES)          // 73728

template <int MODE>
__global__ __launch_bounds__(256, 2) void mma_gemm_kernel(
    const float* __restrict__ bias, float* __restrict__ out)
{
    extern __shared__ char dsm[];
    const __half* __restrict__ Ahh = MODE ? g_ch : g_xh;
    const __half* __restrict__ All = MODE ? g_cl : g_xl;
    const __half* __restrict__ Bhh = MODE ? g_woh : g_wqh;

    const int tid = threadIdx.x;
    const int wid = tid >> 5, lid = tid & 31;
    const int m0 = blockIdx.y * BM, n0 = blockIdx.x * BN;
    const int wm = wid & 3, wn = wid >> 2;

    const uint32_t sbase = smem_u32(dsm);

    // ---- global->smem mapping
    // A: thread t owns one full row t (0..255) = 4 x 16B chunks. rows<128: hi, >=128: lo.
    const int arow = tid;
    const __half* gArow = (arow < 128)
        ? (Ahh + (size_t)(m0 + arow) * KD)
        : (All + (size_t)(m0 + arow - 128) * KD);
    uint32_t dA[4];
    {
        const int sw = (arow >> 1) & 3;
#pragma unroll
        for (int j = 0; j < 4; j++)
            dA[j] = sbase + (uint32_t)(arow * 64 + ((j ^ sw) << 4));
    }
    // B: thread t owns row t>>1, 2 chunks
    const int brow = tid >> 1;
    const int bc0  = (tid & 1) << 1;
    const __half* gBrow = Bhh + (size_t)(n0 + brow) * KD;
    uint32_t dB[2];
    {
        const int sw = (brow >> 1) & 3;
#pragma unroll
        for (int j = 0; j < 2; j++)
            dB[j] = sbase + SA_BYTES + (uint32_t)(brow * 64 + (((bc0 + j) ^ sw) << 4));
    }

    // ---- ldmatrix per-lane addresses (stage-relative), XOR (k16<<5) to step k
    uint32_t aHi[2], aLo[2], bAd[4];
#pragma unroll
    for (int mi = 0; mi < 2; mi++) {
        int r = wm * 32 + mi * 16 + (lid & 15);
        int e0 = (lid >> 4) ^ ((r >> 1) & 3);
        aHi[mi] = sbase + (uint32_t)(r * 64 + (e0 << 4));
        aLo[mi] = aHi[mi] + 8192;           // lo rows at +128*64B
    }
#pragma unroll
    for (int ni = 0; ni < 4; ni++) {
        int r = wn * 64 + ni * 16 + ((lid >> 4) << 3) + (lid & 7);
        int e0 = ((lid >> 3) & 1) ^ ((r >> 1) & 3);
        bAd[ni] = sbase + SA_BYTES + (uint32_t)(r * 64 + (e0 << 4));
    }

    float acc[2][8][4];
#pragma unroll
    for (int i = 0; i < 2; i++)
#pragma unroll
        for (int j = 0; j < 8; j++)
#pragma unroll
            for (int k = 0; k < 4; k++) acc[i][j][k] = 0.f;

    // ---- prologue: stages 0,1
#pragma unroll
    for (int s = 0; s < 2; s++) {
        const int k0 = s * BK;
        const uint32_t so = s * STG_BYTES;
#pragma unroll
        for (int j = 0; j < 4; j++) cpa16(dA[j] + so, gArow + k0 + j * 8);
#pragma unroll
        for (int j = 0; j < 2; j++) cpa16(dB[j] + so, gBrow + k0 + (bc0 + j) * 8);
        CP_COMMIT();
    }

    int stage = 0, nstage = 2;
    for (int kt = 0; kt < NIT; ++kt) {
        CP_WAIT1();
        __syncthreads();

        if (kt + 2 < NIT) {
            const int k0 = (kt + 2) * BK;
            const uint32_t so = nstage * STG_BYTES;
#pragma unroll
            for (int j = 0; j < 4; j++) cpa16(dA[j] + so, gArow + k0 + j * 8);
#pragma unroll
            for (int j = 0; j < 2; j++) cpa16(dB[j] + so, gBrow + k0 + (bc0 + j) * 8);
        }
        CP_COMMIT();

        const uint32_t so = stage * STG_BYTES;
#pragma unroll
        for (int k16 = 0; k16 < 2; k16++) {
            const uint32_t kx = (uint32_t)(k16 << 5);
            uint32_t ah[2][4], al[2][4], br[4][4];
            ldsm4(ah[0], (aHi[0] + so) ^ kx);
            ldsm4(ah[1], (aHi[1] + so) ^ kx);
            ldsm4(al[0], (aLo[0] + so) ^ kx);
            ldsm4(al[1], (aLo[1] + so) ^ kx);
#pragma unroll
            for (int ni = 0; ni < 4; ni++)
                ldsm4(br[ni], (bAd[ni] + so) ^ kx);
            // hi and lo both accumulate into the same acc; B frags reused
#pragma unroll
            for (int mi = 0; mi < 2; mi++)
#pragma unroll
                for (int n8 = 0; n8 < 8; n8++) {
                    mma16816(acc[mi][n8], ah[mi], &br[n8 >> 1][(n8 & 1) << 1]);
                    mma16816(acc[mi][n8], al[mi], &br[n8 >> 1][(n8 & 1) << 1]);
                }
        }
        stage = stage == 2 ? 0 : stage + 1;
        nstage = nstage == 2 ? 0 : nstage + 1;
    }

    // ---- epilogue
    const int row_l = lid >> 2;
    const int col_l = (lid & 3) << 1;
#pragma unroll
    for (int ni = 0; ni < 8; ni++) {
        const int c = n0 + wn * 64 + ni * 8 + col_l;
        const float bx = bias[c], by = bias[c + 1];
#pragma unroll
        for (int mi = 0; mi < 2; mi++) {
            const int r = m0 + wm * 32 + mi * 16 + row_l;
            float2 v0 = make_float2(acc[mi][ni][0] + bx, acc[mi][ni][1] + by);
            float2 v1 = make_float2(acc[mi][ni][2] + bx, acc[mi][ni][3] + by);
            if (MODE == 0) {
                const int part = c >> 10;
                const int hh   = (c & 1023) >> 6;
                const int d    = c & 63;
                const int bb   = r >> 11;
                const int s    = r & 2047;
                float* dst = (part == 0) ? g_q : (part == 1) ? g_k : g_v;
                float* p = dst + ((size_t)(bb * NHEADS + hh) * S_LEN + s) * DHEAD + d;
                *(float2*)p               = v0;
                *(float2*)(p + 8 * DHEAD) = v1;
            } else {
                float* p = out + (size_t)r * DMODEL + c;
                *(float2*)p                = v0;
                *(float2*)(p + 8 * DMODEL) = v1;
            }
        }
    }
}

// ---------------------------------------------------------------------------
// Windowed attention (f32x2 FFMA2); epilogue writes fp16 hi/lo into g_ch/g_cl
// ---------------------------------------------------------------------------
__global__ __launch_bounds__(256, 4) void attn_kernel()
{
    __shared__ float Qt[64][64];
    __shared__ float Kt[64][32];
    __shared__ float Vs[32][64];
    __shared__ float Ps[32][68];

    const int tid = threadIdx.x;
    const int ty  = tid >> 4;
    const int tx  = tid & 15;
    const int q0  = blockIdx.x * 64;
    const int bh  = blockIdx.y;
    const int h   = bh & 15;
    const int b   = bh >> 4;

    const float* __restrict__ Q = g_q + (size_t)bh * S_LEN * DHEAD;
    const float* __restrict__ K = g_k + (size_t)bh * S_LEN * DHEAD;
    const float* __restrict__ V = g_v + (size_t)bh * S_LEN * DHEAD;

    {
        int q  = tid >> 2;
        int d0 = (tid & 3) << 4;
        const float* src = Q + (size_t)(q0 + q) * DHEAD + d0;
#pragma unroll
        for (int i = 0; i < 4; i++) {
            float4 v = *(const float4*)(src + 4 * i);
            Qt[d0 + 4 * i + 0][q] = v.x;
            Qt[d0 + 4 * i + 1][q] = v.y;
            Qt[d0 + 4 * i + 2][q] = v.z;
            Qt[d0 + 4 * i + 3][q] = v.w;
        }
    }

    ull O2[4][2];
    float mrow[4], lrow[4];
#pragma unroll
    for (int i = 0; i < 4; i++) {
        mrow[i] = -1e30f; lrow[i] = 0.f;
        O2[i][0] = 0ull; O2[i][1] = 0ull;
    }
    const int qrow0 = q0 + ty * 4;

    for (int t = 0; t < 10; t++) {
        const int kt0 = q0 + t * 32;
        if (kt0 >= S_LEN) break;
        __syncthreads();
        {
            int kk = tid >> 3;
            int d0 = (tid & 7) << 3;
            int krow = kt0 + kk;
            if (krow > S_LEN - 1) krow = S_LEN - 1;
            const float* ks = K + (size_t)krow * DHEAD + d0;
            float4 k0v = *(const float4*)ks;
            float4 k1v = *(const float4*)(ks + 4);
            Kt[d0 + 0][kk] = k0v.x; Kt[d0 + 1][kk] = k0v.y;
            Kt[d0 + 2][kk] = k0v.z; Kt[d0 + 3][kk] = k0v.w;
            Kt[d0 + 4][kk] = k1v.x; Kt[d0 + 5][kk] = k1v.y;
            Kt[d0 + 6][kk] = k1v.z; Kt[d0 + 7][kk] = k1v.w;
            const float* vsrc = V + (size_t)krow * DHEAD + d0;
            *(float4*)&Vs[kk][d0]     = *(const float4*)vsrc;
            *(float4*)&Vs[kk][d0 + 4] = *(const float4*)(vsrc + 4);
        }
        __syncthreads();

        ull sc2[4];
        sc2[0] = 0ull; sc2[1] = 0ull; sc2[2] = 0ull; sc2[3] = 0ull;
#pragma unroll 16
        for (int d = 0; d < 64; d++) {
            float4 a = *(const float4*)&Qt[d][ty * 4];
            ull k2   = *(const ull*)&Kt[d][tx * 2];
            fma2(sc2[0], pk2(a.x), k2);
            fma2(sc2[1], pk2(a.y), k2);
            fma2(sc2[2], pk2(a.z), k2);
            fma2(sc2[3], pk2(a.w), k2);
        }
        float sc[4][2];
#pragma unroll
        for (int i = 0; i < 4; i++) upk2(sc2[i], sc[i][0], sc[i][1]);

#pragma unroll
        for (int i = 0; i < 4; i++) {
            int qrow = qrow0 + i;
#pragma unroll
            for (int j = 0; j < 2; j++) {
                int krow = kt0 + tx * 2 + j;
                bool keep = (krow >= qrow) && (krow <= qrow + (WIN - 1)) && (krow < S_LEN);
                sc[i][j] = keep ? sc[i][j] * ATT_SCALE : -INFINITY;
            }
        }

#pragma unroll
        for (int i = 0; i < 4; i++) {
            float tmax = fmaxf(sc[i][0], sc[i][1]);
#pragma unroll
            for (int o = 1; o < 16; o <<= 1)
                tmax = fmaxf(tmax, __shfl_xor_sync(0xffffffffu, tmax, o));
            float nm  = fmaxf(mrow[i], tmax);
            float fac = __expf(mrow[i] - nm);
            mrow[i]   = nm;
            float p0 = __expf(sc[i][0] - nm);
            float p1 = __expf(sc[i][1] - nm);
            sc[i][0] = p0; sc[i][1] = p1;
            float tsum = p0 + p1;
#pragma unroll
            for (int o = 1; o < 16; o <<= 1)
                tsum += __shfl_xor_sync(0xffffffffu, tsum, o);
            lrow[i] = lrow[i] * fac + tsum;
            ull f2 = pk2(fac);
            O2[i][0] = mul2(O2[i][0], f2);
            O2[i][1] = mul2(O2[i][1], f2);
        }

#pragma unroll
        for (int i = 0; i < 4; i++) {
            Ps[tx * 2 + 0][ty * 4 + i] = sc[i][0];
            Ps[tx * 2 + 1][ty * 4 + i] = sc[i][1];
        }
        __syncthreads();

#pragma unroll 8
        for (int k = 0; k < 32; k++) {
            float4 pv     = *(const float4*)&Ps[k][ty * 4];
            ulonglong2 vv = *(const ulonglong2*)&Vs[k][tx * 4];
            ull p0 = pk2(pv.x), p1 = pk2(pv.y), p2 = pk2(pv.z), p3 = pk2(pv.w);
            fma2(O2[0][0], p0, vv.x); fma2(O2[0][1], p0, vv.y);
            fma2(O2[1][0], p1, vv.x); fma2(O2[1][1], p1, vv.y);
            fma2(O2[2][0], p2, vv.x); fma2(O2[2][1], p2, vv.y);
            fma2(O2[3][0], p3, vv.x); fma2(O2[3][1], p3, vv.y);
        }
    }

    // Finalize: divide by l, write fp16 hi/lo into g_ch/g_cl
#pragma unroll
    for (int i = 0; i < 4; i++) {
        float inv = 1.0f / lrow[i];
        float f0, f1, f2v, f3v;
        upk2(O2[i][0], f0, f1); upk2(O2[i][1], f2v, f3v);
        f0 *= inv; f1 *= inv; f2v *= inv; f3v *= inv;
        __half h0, h1, h2, h3, l0, l1, l2, l3;
        h_split(f0, h0, l0); h_split(f1, h1, l1);
        h_split(f2v, h2, l2); h_split(f3v, h3, l3);
        int m = b * S_LEN + qrow0 + i;
        size_t o = (size_t)m * KD + h * 64 + tx * 4;
        *(__half2*)(g_ch + o)     = __half2{h0, h1};
        *(__half2*)(g_ch + o + 2) = __half2{h2, h3};
        *(__half2*)(g_cl + o)     = __half2{l0, l1};
        *(__half2*)(g_cl + o + 2) = __half2{l2, l3};
    }
}

// ---------------------------------------------------------------------------
extern "C" void kernel_launch(void* const* d_in, const int* in_sizes, int n_in,
                              void* d_out, int out_size)
{
    const float* x    = (const float*)d_in[0];
    const float* Wqkv = (const float*)d_in[1];
    const float* bqkv = (const float*)d_in[2];
    const float* Wout = (const float*)d_in[3];
    const float* bout = (const float*)d_in[4];
    float* out = (float*)d_out;
    (void)in_sizes; (void)n_in; (void)out_size;

    cudaFuncSetAttribute(mma_gemm_kernel<0>, cudaFuncAttributeMaxDynamicSharedMemorySize, SMEM_DYN);
    cudaFuncSetAttribute(mma_gemm_kernel<1>, cudaFuncAttributeMaxDynamicSharedMemorySize, SMEM_DYN);

    // Prep: fp16 hi/lo split of x; fp16 transpose of weights
    split_x_kernel<<<MROWS * KD / 4 / 256, 256>>>(x);
    wsplit_kernel<0><<<dim3(3 * DMODEL / 32, DMODEL / 32), dim3(32, 8)>>>(Wqkv, 3 * DMODEL);
    wsplit_kernel<1><<<dim3(DMODEL / 32, DMODEL / 32), dim3(32, 8)>>>(Wout, DMODEL);

    // QKV projection: M=4096, N=3072, K=1024 (2-term fp16, shared B)
    mma_gemm_kernel<0><<<dim3(3 * DMODEL / BN, MROWS / BM), 256, SMEM_DYN>>>(bqkv, nullptr);
    // Windowed attention -> g_ch/g_cl
    attn_kernel<<<dim3(S_LEN / 64, BH), 256>>>();
    // Output projection: M=4096, N=1024, K=1024
    mma_gemm_kernel<1><<<dim3(DMODEL / BN, MROWS / BM), 256, SMEM_DYN>>>(bout, out);
}

// round 9
// speedup vs baseline: 3.3433x; 1.4858x over previous
#include <cuda_runtime.h>
#include <cuda_fp16.h>
#include <math.h>
#include <stdint.h>

#define S_LEN 2048
#define DMODEL 1024
#define NHEADS 16
#define DHEAD 64
#define WIN 256
#define BATCH 2
#define BH (BATCH * NHEADS)
#define MROWS (BATCH * S_LEN)
#define KD 1024
#define ATT_SCALE 0.125f

typedef unsigned long long ull;

// ---- packed f32x2 helpers (attention kernel) ----
__device__ __forceinline__ ull pk2(float x) {
    ull r; asm("mov.b64 %0, {%1, %1};" : "=l"(r) : "f"(x)); return r;
}
__device__ __forceinline__ void upk2(ull v, float& x, float& y) {
    asm("mov.b64 {%0, %1}, %2;" : "=f"(x), "=f"(y) : "l"(v));
}
__device__ __forceinline__ void fma2(ull& d, ull a, ull b) {
    asm("fma.rn.f32x2 %0, %1, %2, %0;" : "+l"(d) : "l"(a), "l"(b));
}
__device__ __forceinline__ ull mul2(ull a, ull b) {
    ull r; asm("mul.rn.f32x2 %0, %1, %2;" : "=l"(r) : "l"(a), "l"(b)); return r;
}

// ---- mma.sync / ldmatrix / cp.async helpers (baseline PTX) ----
__device__ __forceinline__ uint32_t smem_u32(const void* p) {
    uint32_t a;
    asm("{ .reg .u64 t; cvta.to.shared.u64 t, %1; cvt.u32.u64 %0, t; }" : "=r"(a) : "l"(p));
    return a;
}
__device__ __forceinline__ void ldsm4(uint32_t* r, uint32_t addr) {
    asm volatile("ldmatrix.sync.aligned.m8n8.x4.shared.b16 {%0,%1,%2,%3}, [%4];"
                 : "=r"(r[0]), "=r"(r[1]), "=r"(r[2]), "=r"(r[3]) : "r"(addr));
}
__device__ __forceinline__ void mma16816(float* d, const uint32_t* a, const uint32_t* b) {
    asm volatile("mma.sync.aligned.m16n8k16.row.col.f32.f16.f16.f32 "
        "{%0,%1,%2,%3}, {%4,%5,%6,%7}, {%8,%9}, {%0,%1,%2,%3};"
        : "+f"(d[0]), "+f"(d[1]), "+f"(d[2]), "+f"(d[3])
        : "r"(a[0]), "r"(a[1]), "r"(a[2]), "r"(a[3]), "r"(b[0]), "r"(b[1]));
}
__device__ __forceinline__ void cpa16(uint32_t dst, const void* src) {
    asm volatile("cp.async.cg.shared.global [%0], [%1], 16;" :: "r"(dst), "l"(src));
}
#define CP_COMMIT() asm volatile("cp.async.commit_group;" ::: "memory")
#define CP_WAIT2()  asm volatile("cp.async.wait_group 2;" ::: "memory")

// Scratch (allocation-free rule: __device__ globals)
__device__ float g_q[BH * S_LEN * DHEAD];
__device__ float g_k[BH * S_LEN * DHEAD];
__device__ float g_v[BH * S_LEN * DHEAD];
__device__ __half g_xh[(size_t)MROWS * KD];           // fp16 x
__device__ __half g_ch[(size_t)MROWS * KD];           // fp16 attention out
__device__ __half g_wqh[(size_t)(3 * DMODEL) * KD];   // W_qkv^T fp16 [3072][1024]
__device__ __half g_woh[(size_t)DMODEL * KD];         // W_out^T fp16 [1024][1024]

// ---------------------------------------------------------------------------
// Convert x [4096][1024] f32 -> g_xh fp16
// ---------------------------------------------------------------------------
__global__ __launch_bounds__(256) void conv_x_kernel(const float* __restrict__ src)
{
    int idx = blockIdx.x * 256 + threadIdx.x;      // one float4 per thread
    int m = idx >> 8;
    int c = (idx & 255) << 2;
    float4 v = *(const float4*)(src + (size_t)m * KD + c);
    size_t o = (size_t)m * KD + c;
    *(__half2*)(g_xh + o)     = __half2{__float2half_rn(v.x), __float2half_rn(v.y)};
    *(__half2*)(g_xh + o + 2) = __half2{__float2half_rn(v.z), __float2half_rn(v.w)};
}

// ---------------------------------------------------------------------------
// Transpose + fp16 convert weights: W [1024][NC] f32 -> dst [NC][1024] fp16
// ---------------------------------------------------------------------------
template <int WHICH>
__global__ __launch_bounds__(256) void wconv_kernel(const float* __restrict__ src, int NC)
{
    __shared__ float tile[32][33];
    int n0 = blockIdx.x * 32, k0 = blockIdx.y * 32;
    int tx = threadIdx.x, ty = threadIdx.y;   // 32 x 8
#pragma unroll
    for (int i = 0; i < 32; i += 8)
        tile[ty + i][tx] = src[(size_t)(k0 + ty + i) * NC + n0 + tx];
    __syncthreads();
    __half* dst = WHICH ? g_woh : g_wqh;
#pragma unroll
    for (int i = 0; i < 32; i += 8) {
        float v = tile[tx][ty + i];            // = src[k0+tx][n0+ty+i]
        int n = n0 + ty + i, k = k0 + tx;
        dst[(size_t)n * KD + k] = __float2half_rn(v);
    }
}

// ---------------------------------------------------------------------------
// fp16 mma.sync GEMM: C[M,N] = A[M,1024] . B[N,1024]^T + bias
// 128x128x32 CTA tiles, 4-stage cp.async pipeline (wait_group 2),
// 8 warps (4M x 2N), warp tile 32x64, 64 f32 acc/thread.
// MODE 0: A=g_xh B=g_wqh, scatter -> g_q/g_k/g_v.  MODE 1: A=g_ch B=g_woh -> out.
// ---------------------------------------------------------------------------
#define BM 128
#define BN 128
#define BK 32
#define NIT 32                  // 1024 / 32
#define SB_OFF 8192             // B tile at +8KB within a stage
#define STG_BYTES 16384         // A 8KB + B 8KB
#define NSTG 4
#define SMEM_DYN (NSTG * STG_BYTES)   // 65536

template <int MODE>
__global__ __launch_bounds__(256, 2) void mma_gemm_kernel(
    const float* __restrict__ bias, float* __restrict__ out)
{
    extern __shared__ char dsm[];
    const __half* __restrict__ Ah = MODE ? g_ch : g_xh;
    const __half* __restrict__ Bh = MODE ? g_woh : g_wqh;

    const int tid = threadIdx.x;
    const int wid = tid >> 5, lid = tid & 31;
    const int m0 = blockIdx.y * BM, n0 = blockIdx.x * BN;
    const int wm = wid & 3, wn = wid >> 2;

    const uint32_t sbase = smem_u32(dsm);

    // ---- global->smem mapping: thread owns row tid>>1, two 16B chunks of A and of B
    const int row = tid >> 1;
    const int c0  = (tid & 1) << 1;
    const int sw  = (row >> 1) & 3;
    const __half* gA = Ah + (size_t)(m0 + row) * KD;
    const __half* gB = Bh + (size_t)(n0 + row) * KD;
    uint32_t dA[2], dB[2];
#pragma unroll
    for (int j = 0; j < 2; j++) {
        dA[j] = sbase + (uint32_t)(row * 64 + (((c0 + j) ^ sw) << 4));
        dB[j] = dA[j] + SB_OFF;
    }

    // ---- ldmatrix per-lane addresses (stage-relative), XOR (k16<<5) to step k
    uint32_t aAd[2], bAd[4];
#pragma unroll
    for (int mi = 0; mi < 2; mi++) {
        int r = wm * 32 + mi * 16 + (lid & 15);
        int e0 = (lid >> 4) ^ ((r >> 1) & 3);
        aAd[mi] = sbase + (uint32_t)(r * 64 + (e0 << 4));
    }
#pragma unroll
    for (int ni = 0; ni < 4; ni++) {
        int r = wn * 64 + ni * 16 + ((lid >> 4) << 3) + (lid & 7);
        int e0 = ((lid >> 3) & 1) ^ ((r >> 1) & 3);
        bAd[ni] = sbase + SB_OFF + (uint32_t)(r * 64 + (e0 << 4));
    }

    float acc[2][8][4];
#pragma unroll
    for (int i = 0; i < 2; i++)
#pragma unroll
        for (int j = 0; j < 8; j++)
#pragma unroll
            for (int k = 0; k < 4; k++) acc[i][j][k] = 0.f;

    // ---- prologue: stages 0,1,2 in flight
#pragma unroll
    for (int s = 0; s < 3; s++) {
        const int k0 = s * BK;
        const uint32_t so = s * STG_BYTES;
        cpa16(dA[0] + so, gA + k0 + c0 * 8);
        cpa16(dA[1] + so, gA + k0 + (c0 + 1) * 8);
        cpa16(dB[0] + so, gB + k0 + c0 * 8);
        cpa16(dB[1] + so, gB + k0 + (c0 + 1) * 8);
        CP_COMMIT();
    }

    for (int kt = 0; kt < NIT; ++kt) {
        CP_WAIT2();                 // stage kt resident; kt+1, kt+2 in flight
        __syncthreads();

        if (kt + 3 < NIT) {         // prefetch stage kt+3 (overwrites stage kt-1: safe post-sync)
            const int k0 = (kt + 3) * BK;
            const uint32_t so = ((kt + 3) & 3) * STG_BYTES;
            cpa16(dA[0] + so, gA + k0 + c0 * 8);
            cpa16(dA[1] + so, gA + k0 + (c0 + 1) * 8);
            cpa16(dB[0] + so, gB + k0 + c0 * 8);
            cpa16(dB[1] + so, gB + k0 + (c0 + 1) * 8);
        }
        CP_COMMIT();

        const uint32_t so = (kt & 3) * STG_BYTES;
#pragma unroll
        for (int k16 = 0; k16 < 2; k16++) {
            const uint32_t kx = (uint32_t)(k16 << 5);
            uint32_t ar[2][4], br[4][4];
            ldsm4(ar[0], (aAd[0] + so) ^ kx);
            ldsm4(ar[1], (aAd[1] + so) ^ kx);
#pragma unroll
            for (int ni = 0; ni < 4; ni++)
                ldsm4(br[ni], (bAd[ni] + so) ^ kx);
#pragma unroll
            for (int mi = 0; mi < 2; mi++)
#pragma unroll
                for (int n8 = 0; n8 < 8; n8++)
                    mma16816(acc[mi][n8], ar[mi], &br[n8 >> 1][(n8 & 1) << 1]);
        }
    }

    // ---- epilogue
    const int row_l = lid >> 2;
    const int col_l = (lid & 3) << 1;
#pragma unroll
    for (int ni = 0; ni < 8; ni++) {
        const int c = n0 + wn * 64 + ni * 8 + col_l;
        const float bx = bias[c], by = bias[c + 1];
#pragma unroll
        for (int mi = 0; mi < 2; mi++) {
            const int r = m0 + wm * 32 + mi * 16 + row_l;
            float2 v0 = make_float2(acc[mi][ni][0] + bx, acc[mi][ni][1] + by);
            float2 v1 = make_float2(acc[mi][ni][2] + bx, acc[mi][ni][3] + by);
            if (MODE == 0) {
                const int part = c >> 10;
                const int hh   = (c & 1023) >> 6;
                const int d    = c & 63;
                const int bb   = r >> 11;
                const int s    = r & 2047;
                float* dst = (part == 0) ? g_q : (part == 1) ? g_k : g_v;
                float* p = dst + ((size_t)(bb * NHEADS + hh) * S_LEN + s) * DHEAD + d;
                *(float2*)p               = v0;
                *(float2*)(p + 8 * DHEAD) = v1;
            } else {
                float* p = out + (size_t)r * DMODEL + c;
                *(float2*)p                = v0;
                *(float2*)(p + 8 * DMODEL) = v1;
            }
        }
    }
}

// ---------------------------------------------------------------------------
// Windowed attention (f32x2 FFMA2); epilogue writes fp16 into g_ch
// ---------------------------------------------------------------------------
__global__ __launch_bounds__(256, 4) void attn_kernel()
{
    __shared__ float Qt[64][64];
    __shared__ float Kt[64][32];
    __shared__ float Vs[32][64];
    __shared__ float Ps[32][68];

    const int tid = threadIdx.x;
    const int ty  = tid >> 4;
    const int tx  = tid & 15;
    const int q0  = blockIdx.x * 64;
    const int bh  = blockIdx.y;
    const int h   = bh & 15;
    const int b   = bh >> 4;

    const float* __restrict__ Q = g_q + (size_t)bh * S_LEN * DHEAD;
    const float* __restrict__ K = g_k + (size_t)bh * S_LEN * DHEAD;
    const float* __restrict__ V = g_v + (size_t)bh * S_LEN * DHEAD;

    {
        int q  = tid >> 2;
        int d0 = (tid & 3) << 4;
        const float* src = Q + (size_t)(q0 + q) * DHEAD + d0;
#pragma unroll
        for (int i = 0; i < 4; i++) {
            float4 v = *(const float4*)(src + 4 * i);
            Qt[d0 + 4 * i + 0][q] = v.x;
            Qt[d0 + 4 * i + 1][q] = v.y;
            Qt[d0 + 4 * i + 2][q] = v.z;
            Qt[d0 + 4 * i + 3][q] = v.w;
        }
    }

    ull O2[4][2];
    float mrow[4], lrow[4];
#pragma unroll
    for (int i = 0; i < 4; i++) {
        mrow[i] = -1e30f; lrow[i] = 0.f;
        O2[i][0] = 0ull; O2[i][1] = 0ull;
    }
    const int qrow0 = q0 + ty * 4;

    for (int t = 0; t < 10; t++) {
        const int kt0 = q0 + t * 32;
        if (kt0 >= S_LEN) break;
        __syncthreads();
        {
            int kk = tid >> 3;
            int d0 = (tid & 7) << 3;
            int krow = kt0 + kk;
            if (krow > S_LEN - 1) krow = S_LEN - 1;
            const float* ks = K + (size_t)krow * DHEAD + d0;
            float4 k0v = *(const float4*)ks;
            float4 k1v = *(const float4*)(ks + 4);
            Kt[d0 + 0][kk] = k0v.x; Kt[d0 + 1][kk] = k0v.y;
            Kt[d0 + 2][kk] = k0v.z; Kt[d0 + 3][kk] = k0v.w;
            Kt[d0 + 4][kk] = k1v.x; Kt[d0 + 5][kk] = k1v.y;
            Kt[d0 + 6][kk] = k1v.z; Kt[d0 + 7][kk] = k1v.w;
            const float* vsrc = V + (size_t)krow * DHEAD + d0;
            *(float4*)&Vs[kk][d0]     = *(const float4*)vsrc;
            *(float4*)&Vs[kk][d0 + 4] = *(const float4*)(vsrc + 4);
        }
        __syncthreads();

        ull sc2[4];
        sc2[0] = 0ull; sc2[1] = 0ull; sc2[2] = 0ull; sc2[3] = 0ull;
#pragma unroll 16
        for (int d = 0; d < 64; d++) {
            float4 a = *(const float4*)&Qt[d][ty * 4];
            ull k2   = *(const ull*)&Kt[d][tx * 2];
            fma2(sc2[0], pk2(a.x), k2);
            fma2(sc2[1], pk2(a.y), k2);
            fma2(sc2[2], pk2(a.z), k2);
            fma2(sc2[3], pk2(a.w), k2);
        }
        float sc[4][2];
#pragma unroll
        for (int i = 0; i < 4; i++) upk2(sc2[i], sc[i][0], sc[i][1]);

#pragma unroll
        for (int i = 0; i < 4; i++) {
            int qrow = qrow0 + i;
#pragma unroll
            for (int j = 0; j < 2; j++) {
                int krow = kt0 + tx * 2 + j;
                bool keep = (krow >= qrow) && (krow <= qrow + (WIN - 1)) && (krow < S_LEN);
                sc[i][j] = keep ? sc[i][j] * ATT_SCALE : -INFINITY;
            }
        }

#pragma unroll
        for (int i = 0; i < 4; i++) {
            float tmax = fmaxf(sc[i][0], sc[i][1]);
#pragma unroll
            for (int o = 1; o < 16; o <<= 1)
                tmax = fmaxf(tmax, __shfl_xor_sync(0xffffffffu, tmax, o));
            float nm  = fmaxf(mrow[i], tmax);
            float fac = __expf(mrow[i] - nm);
            mrow[i]   = nm;
            float p0 = __expf(sc[i][0] - nm);
            float p1 = __expf(sc[i][1] - nm);
            sc[i][0] = p0; sc[i][1] = p1;
            float tsum = p0 + p1;
#pragma unroll
            for (int o = 1; o < 16; o <<= 1)
                tsum += __shfl_xor_sync(0xffffffffu, tsum, o);
            lrow[i] = lrow[i] * fac + tsum;
            ull f2 = pk2(fac);
            O2[i][0] = mul2(O2[i][0], f2);
            O2[i][1] = mul2(O2[i][1], f2);
        }

#pragma unroll
        for (int i = 0; i < 4; i++) {
            Ps[tx * 2 + 0][ty * 4 + i] = sc[i][0];
            Ps[tx * 2 + 1][ty * 4 + i] = sc[i][1];
        }
        __syncthreads();

#pragma unroll 8
        for (int k = 0; k < 32; k++) {
            float4 pv     = *(const float4*)&Ps[k][ty * 4];
            ulonglong2 vv = *(const ulonglong2*)&Vs[k][tx * 4];
            ull p0 = pk2(pv.x), p1 = pk2(pv.y), p2 = pk2(pv.z), p3 = pk2(pv.w);
            fma2(O2[0][0], p0, vv.x); fma2(O2[0][1], p0, vv.y);
            fma2(O2[1][0], p1, vv.x); fma2(O2[1][1], p1, vv.y);
            fma2(O2[2][0], p2, vv.x); fma2(O2[2][1], p2, vv.y);
            fma2(O2[3][0], p3, vv.x); fma2(O2[3][1], p3, vv.y);
        }
    }

    // Finalize: divide by l, write fp16 into g_ch
#pragma unroll
    for (int i = 0; i < 4; i++) {
        float inv = 1.0f / lrow[i];
        float f0, f1, f2v, f3v;
        upk2(O2[i][0], f0, f1); upk2(O2[i][1], f2v, f3v);
        f0 *= inv; f1 *= inv; f2v *= inv; f3v *= inv;
        int m = b * S_LEN + qrow0 + i;
        size_t o = (size_t)m * KD + h * 64 + tx * 4;
        *(__half2*)(g_ch + o)     = __half2{__float2half_rn(f0), __float2half_rn(f1)};
        *(__half2*)(g_ch + o + 2) = __half2{__float2half_rn(f2v), __float2half_rn(f3v)};
    }
}

// ---------------------------------------------------------------------------
extern "C" void kernel_launch(void* const* d_in, const int* in_sizes, int n_in,
                              void* d_out, int out_size)
{
    const float* x    = (const float*)d_in[0];
    const float* Wqkv = (const float*)d_in[1];
    const float* bqkv = (const float*)d_in[2];
    const float* Wout = (const float*)d_in[3];
    const float* bout = (const float*)d_in[4];
    float* out = (float*)d_out;
    (void)in_sizes; (void)n_in; (void)out_size;

    cudaFuncSetAttribute(mma_gemm_kernel<0>, cudaFuncAttributeMaxDynamicSharedMemorySize, SMEM_DYN);
    cudaFuncSetAttribute(mma_gemm_kernel<1>, cudaFuncAttributeMaxDynamicSharedMemorySize, SMEM_DYN);

    // Prep: fp16 conversion of x; fp16 transpose of weights
    conv_x_kernel<<<MROWS * KD / 4 / 256, 256>>>(x);
    wconv_kernel<0><<<dim3(3 * DMODEL / 32, DMODEL / 32), dim3(32, 8)>>>(Wqkv, 3 * DMODEL);
    wconv_kernel<1><<<dim3(DMODEL / 32, DMODEL / 32), dim3(32, 8)>>>(Wout, DMODEL);

    // QKV projection: M=4096, N=3072, K=1024 (fp16 mma.sync)
    mma_gemm_kernel<0><<<dim3(3 * DMODEL / BN, MROWS / BM), 256, SMEM_DYN>>>(bqkv, nullptr);
    // Windowed attention -> g_ch
    attn_kernel<<<dim3(S_LEN / 64, BH), 256>>>();
    // Output projection: M=4096, N=1024, K=1024
    mma_gemm_kernel<1><<<dim3(DMODEL / BN, MROWS / BM), 256, SMEM_DYN>>>(bout, out);
}

// round 10
// speedup vs baseline: 5.4370x; 1.6263x over previous
#include <cuda_runtime.h>
#include <cuda_fp16.h>
#include <math.h>
#include <stdint.h>

#define S_LEN 2048
#define DMODEL 1024
#define NHEADS 16
#define DHEAD 64
#define WIN 256
#define BATCH 2
#define BH (BATCH * NHEADS)
#define MROWS (BATCH * S_LEN)
#define KD 1024
#define ATT_SCALE 0.125f

// ---- mma.sync / ldmatrix / cp.async helpers (baseline PTX) ----
__device__ __forceinline__ uint32_t smem_u32(const void* p) {
    uint32_t a;
    asm("{ .reg .u64 t; cvta.to.shared.u64 t, %1; cvt.u32.u64 %0, t; }" : "=r"(a) : "l"(p));
    return a;
}
__device__ __forceinline__ void ldsm4(uint32_t* r, uint32_t addr) {
    asm volatile("ldmatrix.sync.aligned.m8n8.x4.shared.b16 {%0,%1,%2,%3}, [%4];"
                 : "=r"(r[0]), "=r"(r[1]), "=r"(r[2]), "=r"(r[3]) : "r"(addr));
}
__device__ __forceinline__ void mma16816(float* d, const uint32_t* a, const uint32_t* b) {
    asm volatile("mma.sync.aligned.m16n8k16.row.col.f32.f16.f16.f32 "
        "{%0,%1,%2,%3}, {%4,%5,%6,%7}, {%8,%9}, {%0,%1,%2,%3};"
        : "+f"(d[0]), "+f"(d[1]), "+f"(d[2]), "+f"(d[3])
        : "r"(a[0]), "r"(a[1]), "r"(a[2]), "r"(a[3]), "r"(b[0]), "r"(b[1]));
}
__device__ __forceinline__ void cpa16(uint32_t dst, const void* src) {
    asm volatile("cp.async.cg.shared.global [%0], [%1], 16;" :: "r"(dst), "l"(src));
}
#define CP_COMMIT() asm volatile("cp.async.commit_group;" ::: "memory")
#define CP_WAIT0()  asm volatile("cp.async.wait_group 0;" ::: "memory")
#define CP_WAIT1()  asm volatile("cp.async.wait_group 1;" ::: "memory")
#define CP_WAIT2()  asm volatile("cp.async.wait_group 2;" ::: "memory")

// Scratch (allocation-free rule: __device__ globals)
__device__ __half g_xh[(size_t)MROWS * KD];           // fp16 x
__device__ __half g_ch[(size_t)MROWS * KD];           // fp16 attention out
__device__ __half g_wqh[(size_t)(3 * DMODEL) * KD];   // W_qkv^T fp16 [3072][1024]
__device__ __half g_woh[(size_t)DMODEL * KD];         // W_out^T fp16 [1024][1024]
__device__ __half g_qh[(size_t)BH * S_LEN * DHEAD];   // Q hi  [bh][s][d]
__device__ __half g_ql[(size_t)BH * S_LEN * DHEAD];   // Q lo
__device__ __half g_kh[(size_t)BH * S_LEN * DHEAD];   // K hi
__device__ __half g_kl[(size_t)BH * S_LEN * DHEAD];   // K lo
__device__ __half g_vth[(size_t)BH * DHEAD * S_LEN];  // V^T hi [bh][d][s]
__device__ __half g_vtl[(size_t)BH * DHEAD * S_LEN];  // V^T lo

__device__ __forceinline__ void h_split(float v, __half& hi, __half& lo) {
    hi = __float2half_rn(v);
    lo = __float2half_rn(v - __half2float(hi));
}

// ---------------------------------------------------------------------------
// Convert x [4096][1024] f32 -> g_xh fp16
// ---------------------------------------------------------------------------
__global__ __launch_bounds__(256) void conv_x_kernel(const float* __restrict__ src)
{
    int idx = blockIdx.x * 256 + threadIdx.x;
    int m = idx >> 8;
    int c = (idx & 255) << 2;
    float4 v = *(const float4*)(src + (size_t)m * KD + c);
    size_t o = (size_t)m * KD + c;
    *(__half2*)(g_xh + o)     = __half2{__float2half_rn(v.x), __float2half_rn(v.y)};
    *(__half2*)(g_xh + o + 2) = __half2{__float2half_rn(v.z), __float2half_rn(v.w)};
}

// ---------------------------------------------------------------------------
// Transpose + fp16 convert weights: W [1024][NC] f32 -> dst [NC][1024] fp16
// ---------------------------------------------------------------------------
template <int WHICH>
__global__ __launch_bounds__(256) void wconv_kernel(const float* __restrict__ src, int NC)
{
    __shared__ float tile[32][33];
    int n0 = blockIdx.x * 32, k0 = blockIdx.y * 32;
    int tx = threadIdx.x, ty = threadIdx.y;   // 32 x 8
#pragma unroll
    for (int i = 0; i < 32; i += 8)
        tile[ty + i][tx] = src[(size_t)(k0 + ty + i) * NC + n0 + tx];
    __syncthreads();
    __half* dst = WHICH ? g_woh : g_wqh;
#pragma unroll
    for (int i = 0; i < 32; i += 8) {
        float v = tile[tx][ty + i];
        int n = n0 + ty + i, k = k0 + tx;
        dst[(size_t)n * KD + k] = __float2half_rn(v);
    }
}

// ---------------------------------------------------------------------------
// fp16 mma.sync GEMM (R9-validated): C[M,N] = A[M,1024] . B[N,1024]^T + bias
// MODE 0: A=g_xh B=g_wqh, epilogue splits Q/K to hi/lo fp16, V transposed hi/lo.
// MODE 1: A=g_ch B=g_woh -> fp32 out.
// ---------------------------------------------------------------------------
#define BM 128
#define BN 128
#define BK 32
#define NIT 32
#define SB_OFF 8192
#define STG_BYTES 16384
#define SMEM_DYN (4 * STG_BYTES)

template <int MODE>
__global__ __launch_bounds__(256, 2) void mma_gemm_kernel(
    const float* __restrict__ bias, float* __restrict__ out)
{
    extern __shared__ char dsm[];
    const __half* __restrict__ Ah = MODE ? g_ch : g_xh;
    const __half* __restrict__ Bh = MODE ? g_woh : g_wqh;

    const int tid = threadIdx.x;
    const int wid = tid >> 5, lid = tid & 31;
    const int m0 = blockIdx.y * BM, n0 = blockIdx.x * BN;
    const int wm = wid & 3, wn = wid >> 2;
    const uint32_t sbase = smem_u32(dsm);

    const int row = tid >> 1;
    const int c0  = (tid & 1) << 1;
    const int sw  = (row >> 1) & 3;
    const __half* gA = Ah + (size_t)(m0 + row) * KD;
    const __half* gB = Bh + (size_t)(n0 + row) * KD;
    uint32_t dA[2], dB[2];
#pragma unroll
    for (int j = 0; j < 2; j++) {
        dA[j] = sbase + (uint32_t)(row * 64 + (((c0 + j) ^ sw) << 4));
        dB[j] = dA[j] + SB_OFF;
    }

    uint32_t aAd[2], bAd[4];
#pragma unroll
    for (int mi = 0; mi < 2; mi++) {
        int r = wm * 32 + mi * 16 + (lid & 15);
        int e0 = (lid >> 4) ^ ((r >> 1) & 3);
        aAd[mi] = sbase + (uint32_t)(r * 64 + (e0 << 4));
    }
#pragma unroll
    for (int ni = 0; ni < 4; ni++) {
        int r = wn * 64 + ni * 16 + ((lid >> 4) << 3) + (lid & 7);
        int e0 = ((lid >> 3) & 1) ^ ((r >> 1) & 3);
        bAd[ni] = sbase + SB_OFF + (uint32_t)(r * 64 + (e0 << 4));
    }

    float acc[2][8][4];
#pragma unroll
    for (int i = 0; i < 2; i++)
#pragma unroll
        for (int j = 0; j < 8; j++)
#pragma unroll
            for (int k = 0; k < 4; k++) acc[i][j][k] = 0.f;

#pragma unroll
    for (int s = 0; s < 3; s++) {
        const int k0 = s * BK;
        const uint32_t so = s * STG_BYTES;
        cpa16(dA[0] + so, gA + k0 + c0 * 8);
        cpa16(dA[1] + so, gA + k0 + (c0 + 1) * 8);
        cpa16(dB[0] + so, gB + k0 + c0 * 8);
        cpa16(dB[1] + so, gB + k0 + (c0 + 1) * 8);
        CP_COMMIT();
    }

    for (int kt = 0; kt < NIT; ++kt) {
        CP_WAIT2();
        __syncthreads();
        if (kt + 3 < NIT) {
            const int k0 = (kt + 3) * BK;
            const uint32_t so = ((kt + 3) & 3) * STG_BYTES;
            cpa16(dA[0] + so, gA + k0 + c0 * 8);
            cpa16(dA[1] + so, gA + k0 + (c0 + 1) * 8);
            cpa16(dB[0] + so, gB + k0 + c0 * 8);
            cpa16(dB[1] + so, gB + k0 + (c0 + 1) * 8);
        }
        CP_COMMIT();

        const uint32_t so = (kt & 3) * STG_BYTES;
#pragma unroll
        for (int k16 = 0; k16 < 2; k16++) {
            const uint32_t kx = (uint32_t)(k16 << 5);
            uint32_t ar[2][4], br[4][4];
            ldsm4(ar[0], (aAd[0] + so) ^ kx);
            ldsm4(ar[1], (aAd[1] + so) ^ kx);
#pragma unroll
            for (int ni = 0; ni < 4; ni++)
                ldsm4(br[ni], (bAd[ni] + so) ^ kx);
#pragma unroll
            for (int mi = 0; mi < 2; mi++)
#pragma unroll
                for (int n8 = 0; n8 < 8; n8++)
                    mma16816(acc[mi][n8], ar[mi], &br[n8 >> 1][(n8 & 1) << 1]);
        }
    }

    // ---- epilogue
    const int row_l = lid >> 2;
    const int col_l = (lid & 3) << 1;
#pragma unroll
    for (int ni = 0; ni < 8; ni++) {
        const int c = n0 + wn * 64 + ni * 8 + col_l;
        const float bx = bias[c], by = bias[c + 1];
#pragma unroll
        for (int mi = 0; mi < 2; mi++) {
            const int r = m0 + wm * 32 + mi * 16 + row_l;
            float x00 = acc[mi][ni][0] + bx, x01 = acc[mi][ni][1] + by;
            float x10 = acc[mi][ni][2] + bx, x11 = acc[mi][ni][3] + by;
            if (MODE == 0) {
                const int part = c >> 10;
                const int hh   = (c & 1023) >> 6;
                const int d    = c & 63;
                const int bb   = r >> 11;
                const int s    = r & 2047;
                const int bhi  = bb * NHEADS + hh;
                __half h00, h01, h10, h11, l00, l01, l10, l11;
                h_split(x00, h00, l00); h_split(x01, h01, l01);
                h_split(x10, h10, l10); h_split(x11, h11, l11);
                if (part < 2) {
                    __half* dh = (part == 0 ? g_qh : g_kh) + ((size_t)bhi * S_LEN + s) * DHEAD + d;
                    __half* dl = (part == 0 ? g_ql : g_kl) + ((size_t)bhi * S_LEN + s) * DHEAD + d;
                    *(__half2*)dh                 = __half2{h00, h01};
                    *(__half2*)(dh + 8 * DHEAD)   = __half2{h10, h11};
                    *(__half2*)dl                 = __half2{l00, l01};
                    *(__half2*)(dl + 8 * DHEAD)   = __half2{l10, l11};
                } else {
                    __half* th = g_vth + ((size_t)bhi * DHEAD + d) * S_LEN + s;
                    __half* tl = g_vtl + ((size_t)bhi * DHEAD + d) * S_LEN + s;
                    th[0] = h00; th[S_LEN] = h01; th[8] = h10; th[S_LEN + 8] = h11;
                    tl[0] = l00; tl[S_LEN] = l01; tl[8] = l10; tl[S_LEN + 8] = l11;
                }
            } else {
                float* p = out + (size_t)r * DMODEL + c;
                *(float2*)p                = make_float2(x00, x01);
                *(float2*)(p + 8 * DMODEL) = make_float2(x10, x11);
            }
        }
    }
}

// ---------------------------------------------------------------------------
// Tensor-core flash attention. CTA = (bh, 64-q tile), 128 threads = 4 warps,
// each warp owns 16 q-rows (m16). 32-key tiles, double-buffered cp.async.
// QK: Qh*Kh + Ql*Kh + Qh*Kl.  PV: Ph*Vh + Pl*Vh + Ph*Vl (V pre-transposed).
// smem: Qh 8K | Ql 8K | K[2 stg][hi,lo] 16K | Vt[2 stg][hi,lo] 16K = 48K.
// ---------------------------------------------------------------------------
#define OFF_QL 8192
#define OFF_K  16384
#define OFF_VT 32768

__global__ __launch_bounds__(128, 3) void attn_kernel()
{
    __shared__ __align__(1024) char smbuf[49152];
    const uint32_t sb = smem_u32(smbuf);
    const int tid = threadIdx.x;
    const int lid = tid & 31, wid = tid >> 5;
    const int q0 = blockIdx.x * 64;
    const int bh = blockIdx.y;
    const int hh = bh & 15, bb = bh >> 4;
    const int nT = min(10, (S_LEN - q0) >> 5);

    const __half* Qhp = g_qh + (size_t)bh * S_LEN * DHEAD;
    const __half* Qlp = g_ql + (size_t)bh * S_LEN * DHEAD;
    const __half* Khp = g_kh + (size_t)bh * S_LEN * DHEAD;
    const __half* Klp = g_kl + (size_t)bh * S_LEN * DHEAD;
    const __half* Vhp = g_vth + (size_t)bh * DHEAD * S_LEN;
    const __half* Vlp = g_vtl + (size_t)bh * DHEAD * S_LEN;

    // ---- Q tile cp.async (hi+lo), 64 rows x 128B, swizzle chunk^(r&7)
    {
        int r = tid >> 1, j0 = (tid & 1) * 4;
        const __half* sh = Qhp + (size_t)(q0 + r) * DHEAD;
        const __half* sl = Qlp + (size_t)(q0 + r) * DHEAD;
        uint32_t rb = sb + r * 128;
#pragma unroll
        for (int j = j0; j < j0 + 4; j++) {
            uint32_t o = (uint32_t)((j ^ (r & 7)) << 4);
            cpa16(rb + o, sh + j * 8);
            cpa16(rb + OFF_QL + o, sl + j * 8);
        }
    }
    CP_COMMIT();

    auto load_tile = [&](int t) {
        int kt0 = q0 + t * 32, s = t & 1;
        {   // K tile: 32 rows(key) x 128B, hi+lo
            int r = tid >> 2, j0 = (tid & 3) * 2;
            const __half* sh = Khp + (size_t)(kt0 + r) * DHEAD;
            const __half* sl = Klp + (size_t)(kt0 + r) * DHEAD;
            uint32_t kb = sb + OFF_K + s * 8192 + r * 128;
#pragma unroll
            for (int j = j0; j < j0 + 2; j++) {
                uint32_t o = (uint32_t)((j ^ (r & 7)) << 4);
                cpa16(kb + o, sh + j * 8);
                cpa16(kb + 4096 + o, sl + j * 8);
            }
        }
        {   // Vt tile: 64 rows(d) x 64B, hi+lo, swizzle chunk^((r>>1)&3)
            int r = tid >> 1, j0 = (tid & 1) * 2;
            const __half* sh = Vhp + (size_t)r * S_LEN + kt0;
            const __half* sl = Vlp + (size_t)r * S_LEN + kt0;
            uint32_t vb = sb + OFF_VT + s * 8192 + r * 64;
#pragma unroll
            for (int j = j0; j < j0 + 2; j++) {
                uint32_t o = (uint32_t)((j ^ ((r >> 1) & 3)) << 4);
                cpa16(vb + o, sh + j * 8);
                cpa16(vb + 4096 + o, sl + j * 8);
            }
        }
    };
    load_tile(0); CP_COMMIT();
    load_tile(1); CP_COMMIT();
    CP_WAIT1();            // Q + tile0 resident
    __syncthreads();

    // ---- Q fragments (hi+lo), preloaded for all 4 k16 chunks
    uint32_t qh[4][4], ql[4][4];
    {
        int r = wid * 16 + (lid & 15);
        uint32_t base = (uint32_t)(r * 128 + (((lid >> 4) ^ (r & 7)) << 4));
#pragma unroll
        for (int kc = 0; kc < 4; kc++) {
            ldsm4(qh[kc], (sb + base) ^ (uint32_t)(kc << 5));
            ldsm4(ql[kc], (sb + OFF_QL + base) ^ (uint32_t)(kc << 5));
        }
    }

    // per-lane ldsm offsets for K (128B rows) and Vt (64B rows)
    uint32_t kadr[2], vadr[4];
#pragma unroll
    for (int ni = 0; ni < 2; ni++) {
        int r = ni * 16 + ((lid >> 4) << 3) + (lid & 7);
        kadr[ni] = (uint32_t)(r * 128 + ((((lid >> 3) & 1) ^ (r & 7)) << 4));
    }
#pragma unroll
    for (int ni = 0; ni < 4; ni++) {
        int r = ni * 16 + ((lid >> 4) << 3) + (lid & 7);
        vadr[ni] = (uint32_t)(r * 64 + ((((lid >> 3) & 1) ^ ((r >> 1) & 3)) << 4));
    }

    float od[8][4];
#pragma unroll
    for (int i = 0; i < 8; i++) { od[i][0] = od[i][1] = od[i][2] = od[i][3] = 0.f; }
    float m0 = -1e30f, m1 = -1e30f, l0 = 0.f, l1 = 0.f;
    const int qr0 = q0 + wid * 16 + (lid >> 2);
    const int qr1 = qr0 + 8;
    const int kcol = (lid & 3) << 1;
    const int wlo = q0 + wid * 16;

    for (int t = 0; t < nT; ++t) {
        const int kt0 = q0 + t * 32, s = t & 1;
        const bool active = (kt0 + 31 >= wlo) && (kt0 <= wlo + 15 + WIN - 1);
        if (active) {
            // ---- scores S = Q.K^T (3-term)
            float sc[4][4];
#pragma unroll
            for (int i = 0; i < 4; i++) { sc[i][0] = sc[i][1] = sc[i][2] = sc[i][3] = 0.f; }
            const uint32_t kbh = sb + OFF_K + s * 8192;
            const uint32_t kbl = kbh + 4096;
#pragma unroll
            for (int kc = 0; kc < 4; kc++) {
                const uint32_t kx = (uint32_t)(kc << 5);
                uint32_t kh2[2][4], kl2[2][4];
                ldsm4(kh2[0], (kbh + kadr[0]) ^ kx);
                ldsm4(kh2[1], (kbh + kadr[1]) ^ kx);
                ldsm4(kl2[0], (kbl + kadr[0]) ^ kx);
                ldsm4(kl2[1], (kbl + kadr[1]) ^ kx);
#pragma unroll
                for (int ni = 0; ni < 2; ni++)
#pragma unroll
                    for (int hf = 0; hf < 2; hf++) {
                        int n8 = ni * 2 + hf;
                        mma16816(sc[n8], qh[kc], &kh2[ni][hf * 2]);
                        mma16816(sc[n8], ql[kc], &kh2[ni][hf * 2]);
                        mma16816(sc[n8], qh[kc], &kl2[ni][hf * 2]);
                    }
            }
            // ---- mask + scale
#pragma unroll
            for (int n8 = 0; n8 < 4; n8++) {
#pragma unroll
                for (int jj = 0; jj < 2; jj++) {
                    int key = kt0 + n8 * 8 + kcol + jj;
                    sc[n8][jj]     = (key >= qr0 && key < qr0 + WIN) ? sc[n8][jj] * ATT_SCALE : -INFINITY;
                    sc[n8][2 + jj] = (key >= qr1 && key < qr1 + WIN) ? sc[n8][2 + jj] * ATT_SCALE : -INFINITY;
                }
            }
            // ---- online softmax (rows live on lane quads: 2 shfl reduce)
            float t0 = fmaxf(fmaxf(sc[0][0], sc[0][1]), fmaxf(sc[1][0], sc[1][1]));
            t0 = fmaxf(t0, fmaxf(fmaxf(sc[2][0], sc[2][1]), fmaxf(sc[3][0], sc[3][1])));
            float t1 = fmaxf(fmaxf(sc[0][2], sc[0][3]), fmaxf(sc[1][2], sc[1][3]));
            t1 = fmaxf(t1, fmaxf(fmaxf(sc[2][2], sc[2][3]), fmaxf(sc[3][2], sc[3][3])));
            t0 = fmaxf(t0, __shfl_xor_sync(0xffffffffu, t0, 1));
            t0 = fmaxf(t0, __shfl_xor_sync(0xffffffffu, t0, 2));
            t1 = fmaxf(t1, __shfl_xor_sync(0xffffffffu, t1, 1));
            t1 = fmaxf(t1, __shfl_xor_sync(0xffffffffu, t1, 2));
            float nm0 = fmaxf(m0, t0), nm1 = fmaxf(m1, t1);
            float f0 = __expf(m0 - nm0), f1 = __expf(m1 - nm1);
            m0 = nm0; m1 = nm1;
            float s0 = 0.f, s1 = 0.f;
#pragma unroll
            for (int n8 = 0; n8 < 4; n8++) {
                sc[n8][0] = __expf(sc[n8][0] - nm0); s0 += sc[n8][0];
                sc[n8][1] = __expf(sc[n8][1] - nm0); s0 += sc[n8][1];
                sc[n8][2] = __expf(sc[n8][2] - nm1); s1 += sc[n8][2];
                sc[n8][3] = __expf(sc[n8][3] - nm1); s1 += sc[n8][3];
            }
            s0 += __shfl_xor_sync(0xffffffffu, s0, 1);
            s0 += __shfl_xor_sync(0xffffffffu, s0, 2);
            s1 += __shfl_xor_sync(0xffffffffu, s1, 1);
            s1 += __shfl_xor_sync(0xffffffffu, s1, 2);
            l0 = l0 * f0 + s0; l1 = l1 * f1 + s1;
#pragma unroll
            for (int n8 = 0; n8 < 8; n8++) {
                od[n8][0] *= f0; od[n8][1] *= f0;
                od[n8][2] *= f1; od[n8][3] *= f1;
            }
            // ---- P fragments (register repack, hi+lo)
            uint32_t ph[2][4], pl[2][4];
#pragma unroll
            for (int kp = 0; kp < 2; kp++)
#pragma unroll
                for (int rg = 0; rg < 4; rg++) {
                    int n8 = kp * 2 + (rg >> 1);
                    float pa = sc[n8][(rg & 1) * 2 + 0];
                    float pb = sc[n8][(rg & 1) * 2 + 1];
                    __half ha = __float2half_rn(pa), hb = __float2half_rn(pb);
                    ph[kp][rg] = ((uint32_t)__half_as_ushort(hb) << 16) | __half_as_ushort(ha);
                    __half la = __float2half_rn(pa - __half2float(ha));
                    __half lb = __float2half_rn(pb - __half2float(hb));
                    pl[kp][rg] = ((uint32_t)__half_as_ushort(lb) << 16) | __half_as_ushort(la);
                }
            // ---- O += P.V (3-term)
            const uint32_t vbh = sb + OFF_VT + s * 8192;
            const uint32_t vbl = vbh + 4096;
#pragma unroll
            for (int kp = 0; kp < 2; kp++) {
                const uint32_t kx = (uint32_t)(kp << 5);
                uint32_t vh2[4][4], vl2[4][4];
#pragma unroll
                for (int ni = 0; ni < 4; ni++) {
                    ldsm4(vh2[ni], (vbh + vadr[ni]) ^ kx);
                    ldsm4(vl2[ni], (vbl + vadr[ni]) ^ kx);
                }
#pragma unroll
                for (int ni = 0; ni < 4; ni++)
#pragma unroll
                    for (int hf = 0; hf < 2; hf++) {
                        int n8 = ni * 2 + hf;
                        mma16816(od[n8], ph[kp], &vh2[ni][hf * 2]);
                        mma16816(od[n8], pl[kp], &vh2[ni][hf * 2]);
                        mma16816(od[n8], ph[kp], &vl2[ni][hf * 2]);
                    }
            }
        }
        __syncthreads();
        if (t + 1 < nT) {
            if (t + 2 < nT) { load_tile(t + 2); CP_COMMIT(); CP_WAIT1(); }
            else            { CP_WAIT0(); }
            __syncthreads();
        }
    }

    // ---- finalize -> g_ch fp16 [m][KD]
    const float inv0 = 1.0f / l0, inv1 = 1.0f / l1;
    const size_t o0 = ((size_t)(bb * S_LEN + qr0)) * KD + hh * 64;
    const size_t o1 = ((size_t)(bb * S_LEN + qr1)) * KD + hh * 64;
#pragma unroll
    for (int n8 = 0; n8 < 8; n8++) {
        int d = n8 * 8 + kcol;
        *(__half2*)(g_ch + o0 + d) =
            __half2{__float2half_rn(od[n8][0] * inv0), __float2half_rn(od[n8][1] * inv0)};
        *(__half2*)(g_ch + o1 + d) =
            __half2{__float2half_rn(od[n8][2] * inv1), __float2half_rn(od[n8][3] * inv1)};
    }
}

// ---------------------------------------------------------------------------
extern "C" void kernel_launch(void* const* d_in, const int* in_sizes, int n_in,
                              void* d_out, int out_size)
{
    const float* x    = (const float*)d_in[0];
    const float* Wqkv = (const float*)d_in[1];
    const float* bqkv = (const float*)d_in[2];
    const float* Wout = (const float*)d_in[3];
    const float* bout = (const float*)d_in[4];
    float* out = (float*)d_out;
    (void)in_sizes; (void)n_in; (void)out_size;

    cudaFuncSetAttribute(mma_gemm_kernel<0>, cudaFuncAttributeMaxDynamicSharedMemorySize, SMEM_DYN);
    cudaFuncSetAttribute(mma_gemm_kernel<1>, cudaFuncAttributeMaxDynamicSharedMemorySize, SMEM_DYN);

    conv_x_kernel<<<MROWS * KD / 4 / 256, 256>>>(x);
    wconv_kernel<0><<<dim3(3 * DMODEL / 32, DMODEL / 32), dim3(32, 8)>>>(Wqkv, 3 * DMODEL);
    wconv_kernel<1><<<dim3(DMODEL / 32, DMODEL / 32), dim3(32, 8)>>>(Wout, DMODEL);

    // QKV projection: epilogue emits Q/K hi+lo fp16 and transposed V hi+lo
    mma_gemm_kernel<0><<<dim3(3 * DMODEL / BN, MROWS / BM), 256, SMEM_DYN>>>(bqkv, nullptr);
    // Tensor-core flash attention -> g_ch
    attn_kernel<<<dim3(S_LEN / 64, BH), 128>>>();
    // Output projection
    mma_gemm_kernel<1><<<dim3(DMODEL / BN, MROWS / BM), 256, SMEM_DYN>>>(bout, out);
}